// round 8
// baseline (speedup 1.0000x reference)
#include <cuda_runtime.h>
#include <cstdint>
#include <math_constants.h>

#define NV   4096
#define DV   256
#define TK   20
#define TKI  10
#define NSEL 30
#define MLAB 5
#define NW   (NV/32)
#define NCHUNK 64
#define NI   26          // coarse intra candidates (incl self)
#define NE   14          // coarse inter candidates
#define NC   (NI + NE)   // 40

typedef unsigned long long ull;
#define MSB (1ull << 63)

// -------- scratch (static device globals; no allocation) --------
__device__ float    g_sim[(size_t)NV * NV];   // 64 MB (coarse tf32 sim)
__device__ int      g_cand[NV * NC];
__device__ int      g_knn[NV * NSEL];
__device__ unsigned g_bits[NV * NW];

// ============================================================================
// Phase 1: COARSE sim = E*E^T via single-term tf32 mma.sync (err ~5e-3 abs).
// Only candidate-set selection depends on this; exact rescore fixes ranks.
// CTA 128x128 tile; 8 warps (4x2), warp tile 32x64. Upper-tri + mirror.
// ============================================================================
#define SLS 136
#define SLAB (32 * SLS)
#define GSMEM_FLOATS (2 * SLAB)        // A0, B0
#define GSMEM_BYTES (GSMEM_FLOATS * 4) // 34816 B
#define TRS 132                        // transpose staging stride (div by 4)

__device__ __forceinline__ uint32_t tf32of(float x) {
    uint32_t u;
    asm("cvt.rna.tf32.f32 %0, %1;" : "=r"(u) : "f"(x));
    return u;
}
__device__ __forceinline__ uint32_t fbits(float x) { return __float_as_uint(x); }

__device__ __forceinline__ void mma_tf32(float d[4], const uint32_t a[4],
                                         uint32_t b0, uint32_t b1) {
    asm volatile(
        "mma.sync.aligned.m16n8k8.row.col.f32.tf32.tf32.f32 "
        "{%0,%1,%2,%3}, {%4,%5,%6,%7}, {%8,%9}, {%0,%1,%2,%3};"
        : "+f"(d[0]), "+f"(d[1]), "+f"(d[2]), "+f"(d[3])
        : "r"(a[0]), "r"(a[1]), "r"(a[2]), "r"(a[3]), "r"(b0), "r"(b1));
}

__global__ void __launch_bounds__(256, 2) gemm_tf32_kernel(const float* __restrict__ E) {
    int bx = blockIdx.x;
    int by = blockIdx.y;
    if (bx < by) return;

    extern __shared__ float sm[];
    float* A0 = sm;
    float* B0 = sm + SLAB;

    int tid = threadIdx.x;
    int lane = tid & 31;
    int wid = tid >> 5;
    int warpM = wid & 3;
    int warpN = wid >> 2;

    int rowBase = by * 128;
    int colBase = bx * 128;

    float acc[2][8][4];
#pragma unroll
    for (int mt = 0; mt < 2; mt++)
#pragma unroll
        for (int nt = 0; nt < 8; nt++)
#pragma unroll
            for (int g = 0; g < 4; g++) acc[mt][nt][g] = 0.0f;

    int fr = lane >> 2;
    int fc = lane & 3;

#pragma unroll 1
    for (int chunk = 0; chunk < 8; chunk++) {
        int k0 = chunk * 32;
#pragma unroll
        for (int ii = 0; ii < 4; ii++) {
            int it = tid + ii * 256;
            int r = it >> 3;
            int c4 = (it & 7) * 4;
            float4 va = __ldg((const float4*)&E[(size_t)(rowBase + r) * DV + k0 + c4]);
            float4 vb = __ldg((const float4*)&E[(size_t)(colBase + r) * DV + k0 + c4]);
            float ax[4] = {va.x, va.y, va.z, va.w};
            float bxv[4] = {vb.x, vb.y, vb.z, vb.w};
#pragma unroll
            for (int j = 0; j < 4; j++) {
                int kk = c4 + j;
                A0[kk * SLS + r] = __uint_as_float(tf32of(ax[j]));
                B0[kk * SLS + r] = __uint_as_float(tf32of(bxv[j]));
            }
        }
        __syncthreads();

#pragma unroll
        for (int ks = 0; ks < 4; ks++) {
            int kk = ks * 8;
            uint32_t aF[2][4];
#pragma unroll
            for (int mt = 0; mt < 2; mt++) {
                int m = warpM * 32 + mt * 16;
                aF[mt][0] = fbits(A0[(kk + fc) * SLS + m + fr]);
                aF[mt][1] = fbits(A0[(kk + fc) * SLS + m + fr + 8]);
                aF[mt][2] = fbits(A0[(kk + fc + 4) * SLS + m + fr]);
                aF[mt][3] = fbits(A0[(kk + fc + 4) * SLS + m + fr + 8]);
            }
#pragma unroll
            for (int nt = 0; nt < 8; nt++) {
                int n = warpN * 64 + nt * 8 + fr;
                uint32_t b0 = fbits(B0[(kk + fc) * SLS + n]);
                uint32_t b1 = fbits(B0[(kk + fc + 4) * SLS + n]);
#pragma unroll
                for (int mt = 0; mt < 2; mt++)
                    mma_tf32(acc[mt][nt], aF[mt], b0, b1);
            }
        }
        __syncthreads();
    }

    int c2 = (lane & 3) * 2;
#pragma unroll
    for (int mt = 0; mt < 2; mt++) {
#pragma unroll
        for (int nt = 0; nt < 8; nt++) {
            int row = rowBase + warpM * 32 + mt * 16 + fr;
            int col = colBase + warpN * 64 + nt * 8 + c2;
            *(float2*)&g_sim[(size_t)row * NV + col] =
                make_float2(acc[mt][nt][0], acc[mt][nt][1]);
            *(float2*)&g_sim[(size_t)(row + 8) * NV + col] =
                make_float2(acc[mt][nt][2], acc[mt][nt][3]);
        }
    }

    if (bx > by) {
#pragma unroll 1
        for (int half = 0; half < 2; half++) {
            __syncthreads();
            if (warpN == half) {
#pragma unroll
                for (int mt = 0; mt < 2; mt++) {
#pragma unroll
                    for (int nt = 0; nt < 8; nt++) {
                        int lr = warpM * 32 + mt * 16 + fr;
                        int lc = nt * 8 + c2;
                        sm[lc * TRS + lr]            = acc[mt][nt][0];
                        sm[(lc + 1) * TRS + lr]      = acc[mt][nt][1];
                        sm[lc * TRS + lr + 8]        = acc[mt][nt][2];
                        sm[(lc + 1) * TRS + lr + 8]  = acc[mt][nt][3];
                    }
                }
            }
            __syncthreads();
#pragma unroll
            for (int ii = 0; ii < 8; ii++) {
                int it = tid + ii * 256;
                int c = it >> 5;
                int g = it & 31;
                int j = colBase + half * 64 + c;
                float4 v = *(float4*)&sm[c * TRS + g * 4];
                *(float4*)&g_sim[(size_t)j * NV + rowBase + g * 4] = v;
            }
        }
    }
}

// ============================================================================
// Phase 2: coarse tournament top-k -> candidate lists (NI intra + NE inter)
// ============================================================================
__device__ __forceinline__ unsigned f2ord(float f) {
    unsigned b = __float_as_uint(f);
    return (b & 0x80000000u) ? ~b : (b | 0x80000000u);
}
__device__ __forceinline__ ull warp_max_bfly(ull m) {
#pragma unroll
    for (int o = 16; o > 0; o >>= 1) {
        ull other = __shfl_xor_sync(0xffffffffu, m, o);
        if (other > m) m = other;
    }
    return m;
}

__global__ void __launch_bounds__(256) topk_kernel(const int* __restrict__ bid) {
    int i = blockIdx.x;
    int tid = threadIdx.x;
    int lane = tid & 31;
    int wid = tid >> 5;

    __shared__ ull keys[NV];
    __shared__ ull cmax[NCHUNK];
    __shared__ int chosen[NC];

    int myb = __ldg(&bid[i]);

    const float4* row4 = (const float4*)&g_sim[(size_t)i * NV];
    const int4*   bid4 = (const int4*)bid;
    for (int t = tid; t < NV / 4; t += 256) {
        float4 v = row4[t];
        int4   g = __ldg(&bid4[t]);
        int j0 = t * 4;
        keys[j0 + 0] = ((g.x == myb) ? MSB : 0) | ((ull)f2ord(v.x) << 13) | (unsigned)(NV - (j0 + 0));
        keys[j0 + 1] = ((g.y == myb) ? MSB : 0) | ((ull)f2ord(v.y) << 13) | (unsigned)(NV - (j0 + 1));
        keys[j0 + 2] = ((g.z == myb) ? MSB : 0) | ((ull)f2ord(v.z) << 13) | (unsigned)(NV - (j0 + 2));
        keys[j0 + 3] = ((g.w == myb) ? MSB : 0) | ((ull)f2ord(v.w) << 13) | (unsigned)(NV - (j0 + 3));
    }
    __syncthreads();

#pragma unroll 1
    for (int phase = 0; phase < 2; phase++) {
        ull xm = phase ? MSB : 0ull;
        int cnt  = phase ? NE : NI;
        int base = phase ? NI : 0;

#pragma unroll
        for (int cc = 0; cc < 8; cc++) {
            int c = wid * 8 + cc;
            ull a = keys[c * 64 + lane] ^ xm;
            ull b = keys[c * 64 + 32 + lane] ^ xm;
            ull m = a > b ? a : b;
            m = warp_max_bfly(m);
            if (lane == 0) cmax[c] = m;
        }
        __syncthreads();

        if (wid == 0) {
#pragma unroll 1
            for (int t = 0; t < cnt; t++) {
                ull a = cmax[lane];
                ull b = cmax[lane + 32];
                ull m = a > b ? a : b;
                m = warp_max_bfly(m);
                int j = NV - (int)(m & 0x1FFFull);
                int c = j >> 6;
                if (lane == 0) {
                    chosen[base + t] = j;
                    keys[j] = MSB;
                }
                __syncwarp();
                ull ra = keys[c * 64 + lane] ^ xm;
                ull rb = keys[c * 64 + 32 + lane] ^ xm;
                ull rm = ra > rb ? ra : rb;
                rm = warp_max_bfly(rm);
                if (lane == 0) cmax[c] = rm;
                __syncwarp();
            }
        }
        __syncthreads();
    }

    if (tid < NC) g_cand[i * NC + tid] = chosen[tid];
}

// ============================================================================
// Phase 3: EXACT rescore. Recompute candidate dots with k-ascending sequential
// fp32 fmaf (bit-identical to the proven-exact FFMA gemm), rank exactly,
// emit knn + membership bitset. 64 threads per row, 4 rows per block.
// ============================================================================
__global__ void __launch_bounds__(256) rescore_kernel(const float* __restrict__ E) {
    int tid = threadIdx.x;
    int grp = tid >> 6;                 // row group 0..3
    int sub = tid & 63;
    int row = blockIdx.x * 4 + grp;

    __shared__ float4 EiS[4][64];       // row embedding
    __shared__ int    candS[4][NC];
    __shared__ ull    keyS[4][NC];
    __shared__ int    knnS[4][NSEL];

    // load E_row and candidates
    EiS[grp][sub] = __ldg((const float4*)&E[(size_t)row * DV] + sub);
    if (sub < NC) candS[grp][sub] = g_cand[row * NC + sub];
    __syncthreads();

    // exact sequential dot per candidate
    if (sub < NC) {
        int j = candS[grp][sub];
        const float4* Ej4 = (const float4*)&E[(size_t)j * DV];
        const float* Ei = (const float*)&EiS[grp][0];
        float acc = 0.0f;
#pragma unroll 4
        for (int k4 = 0; k4 < 64; k4++) {
            float4 b = __ldg(&Ej4[k4]);
            acc = fmaf(Ei[k4 * 4 + 0], b.x, acc);
            acc = fmaf(Ei[k4 * 4 + 1], b.y, acc);
            acc = fmaf(Ei[k4 * 4 + 2], b.z, acc);
            acc = fmaf(Ei[k4 * 4 + 3], b.w, acc);
        }
        keyS[grp][sub] = ((ull)f2ord(acc) << 13) | (unsigned)(NV - j);
    }
    __syncthreads();

    // exact rank within phase (keys unique -> strict compare)
    if (sub < NC) {
        int lo = (sub < NI) ? 0 : NI;
        int hi = (sub < NI) ? NI : NC;
        ull mykey = keyS[grp][sub];
        int r = 0;
        for (int u = lo; u < hi; u++)
            if (keyS[grp][u] > mykey) r++;
        int j = candS[grp][sub];
        if (sub < NI) {
            if (r >= 1 && r <= TK) knnS[grp][r - 1] = j;     // drop rank 0 (self)
        } else {
            if (r < TKI) knnS[grp][TK + r] = j;
        }
    }
    __syncthreads();

    if (sub < NSEL) g_knn[row * NSEL + sub] = knnS[grp][sub];

    // membership bitset: each thread owns 2 words
    unsigned b0 = 0, b1 = 0;
    int w0 = sub * 2;
#pragma unroll
    for (int t = 0; t < NSEL; t++) {
        int j = knnS[grp][t];
        int wi = j >> 5;
        unsigned bit = 1u << (j & 31);
        if (wi == w0) b0 |= bit;
        if (wi == w0 + 1) b1 |= bit;
    }
    g_bits[row * NW + w0] = b0;
    g_bits[row * NW + w0 + 1] = b1;
}

// ============================================================================
// Phase 4: mutual check -> scatter locality + all_close
// ============================================================================
__global__ void __launch_bounds__(256) finalize_kernel(
    const float* __restrict__ adj, const int* __restrict__ cl,
    float* __restrict__ out) {
    int id = blockIdx.x * blockDim.x + threadIdx.x;
    if (id >= NV * NSEL) return;
    int i = id / NSEL;
    int j = g_knn[id];

    bool mut = (j != i) && ((g_bits[j * NW + (i >> 5)] >> (i & 31)) & 1u);
    if (mut) out[(size_t)i * NV + j] = adj[(size_t)i * NV + j];

    bool ac = mut;
    if (!ac) {
        ac = true;
#pragma unroll
        for (int m = 0; m < MLAB; m++)
            if (cl[m * NV + i] != cl[m * NV + j]) ac = false;
    }
    out[(size_t)NV * NV + id] = ac ? 1.0f : 0.0f;
}

// ============================================================================
extern "C" void kernel_launch(void* const* d_in, const int* in_sizes, int n_in,
                              void* d_out, int out_size) {
    const float* adj = (const float*)d_in[0];
    const float* E   = (const float*)d_in[1];
    const int*   bid = (const int*)d_in[2];
    const int*   cl  = (const int*)d_in[3];
    float* out = (float*)d_out;

    cudaFuncSetAttribute(gemm_tf32_kernel, cudaFuncAttributeMaxDynamicSharedMemorySize,
                         GSMEM_BYTES);

    cudaMemsetAsync(out, 0, (size_t)NV * NV * sizeof(float));
    dim3 grid(NV / 128, NV / 128);
    gemm_tf32_kernel<<<grid, 256, GSMEM_BYTES>>>(E);
    topk_kernel<<<NV, 256>>>(bid);
    rescore_kernel<<<NV / 4, 256>>>(E);
    finalize_kernel<<<(NV * NSEL + 255) / 256, 256>>>(adj, cl, out);
}

// round 9
// speedup vs baseline: 1.3973x; 1.3973x over previous
#include <cuda_runtime.h>
#include <cuda_fp16.h>
#include <cstdint>
#include <math_constants.h>

#define NV   4096
#define DV   256
#define TK   20
#define TKI  10
#define NSEL 30
#define MLAB 5
#define NW   (NV/32)
#define NCHUNK 64
#define NI   26          // coarse intra candidates (incl self)
#define NE   14          // coarse inter candidates
#define NC   (NI + NE)   // 40

typedef unsigned long long ull;

// -------- scratch (static device globals; no allocation) --------
__device__ __half   g_simh[(size_t)NV * NV];  // 32 MB coarse sim (fp16)
__device__ int      g_cand[NV * NC];
__device__ int      g_knn[NV * NSEL];
__device__ unsigned g_bits[NV * NW];

// ============================================================================
// Phase 1: COARSE sim = E*E^T via single-term tf32 mma.sync, stored as fp16.
// CTA 128x128 tile; 8 warps (4x2), warp tile 32x64. Upper-tri + mirror.
// ============================================================================
#define SLS 136
#define SLAB (32 * SLS)
#define GSMEM_FLOATS (2 * SLAB)        // A0, B0
#define GSMEM_BYTES (GSMEM_FLOATS * 4) // 34816 B
#define TRS 132                        // float transpose staging stride (div 4)

__device__ __forceinline__ uint32_t tf32of(float x) {
    uint32_t u;
    asm("cvt.rna.tf32.f32 %0, %1;" : "=r"(u) : "f"(x));
    return u;
}
__device__ __forceinline__ uint32_t fbits(float x) { return __float_as_uint(x); }

__device__ __forceinline__ void mma_tf32(float d[4], const uint32_t a[4],
                                         uint32_t b0, uint32_t b1) {
    asm volatile(
        "mma.sync.aligned.m16n8k8.row.col.f32.tf32.tf32.f32 "
        "{%0,%1,%2,%3}, {%4,%5,%6,%7}, {%8,%9}, {%0,%1,%2,%3};"
        : "+f"(d[0]), "+f"(d[1]), "+f"(d[2]), "+f"(d[3])
        : "r"(a[0]), "r"(a[1]), "r"(a[2]), "r"(a[3]), "r"(b0), "r"(b1));
}

__global__ void __launch_bounds__(256, 2) gemm_tf32_kernel(const float* __restrict__ E) {
    int bx = blockIdx.x;
    int by = blockIdx.y;
    if (bx < by) return;

    extern __shared__ float sm[];
    float* A0 = sm;
    float* B0 = sm + SLAB;

    int tid = threadIdx.x;
    int lane = tid & 31;
    int wid = tid >> 5;
    int warpM = wid & 3;
    int warpN = wid >> 2;

    int rowBase = by * 128;
    int colBase = bx * 128;

    float acc[2][8][4];
#pragma unroll
    for (int mt = 0; mt < 2; mt++)
#pragma unroll
        for (int nt = 0; nt < 8; nt++)
#pragma unroll
            for (int g = 0; g < 4; g++) acc[mt][nt][g] = 0.0f;

    int fr = lane >> 2;
    int fc = lane & 3;

#pragma unroll 1
    for (int chunk = 0; chunk < 8; chunk++) {
        int k0 = chunk * 32;
#pragma unroll
        for (int ii = 0; ii < 4; ii++) {
            int it = tid + ii * 256;
            int r = it >> 3;
            int c4 = (it & 7) * 4;
            float4 va = __ldg((const float4*)&E[(size_t)(rowBase + r) * DV + k0 + c4]);
            float4 vb = __ldg((const float4*)&E[(size_t)(colBase + r) * DV + k0 + c4]);
            float ax[4] = {va.x, va.y, va.z, va.w};
            float bxv[4] = {vb.x, vb.y, vb.z, vb.w};
#pragma unroll
            for (int j = 0; j < 4; j++) {
                int kk = c4 + j;
                A0[kk * SLS + r] = __uint_as_float(tf32of(ax[j]));
                B0[kk * SLS + r] = __uint_as_float(tf32of(bxv[j]));
            }
        }
        __syncthreads();

#pragma unroll
        for (int ks = 0; ks < 4; ks++) {
            int kk = ks * 8;
            uint32_t aF[2][4];
#pragma unroll
            for (int mt = 0; mt < 2; mt++) {
                int m = warpM * 32 + mt * 16;
                aF[mt][0] = fbits(A0[(kk + fc) * SLS + m + fr]);
                aF[mt][1] = fbits(A0[(kk + fc) * SLS + m + fr + 8]);
                aF[mt][2] = fbits(A0[(kk + fc + 4) * SLS + m + fr]);
                aF[mt][3] = fbits(A0[(kk + fc + 4) * SLS + m + fr + 8]);
            }
#pragma unroll
            for (int nt = 0; nt < 8; nt++) {
                int n = warpN * 64 + nt * 8 + fr;
                uint32_t b0 = fbits(B0[(kk + fc) * SLS + n]);
                uint32_t b1 = fbits(B0[(kk + fc + 4) * SLS + n]);
#pragma unroll
                for (int mt = 0; mt < 2; mt++)
                    mma_tf32(acc[mt][nt], aF[mt], b0, b1);
            }
        }
        __syncthreads();
    }

    // ---- direct write as fp16 (covers diag tile fully) ----
    int c2 = (lane & 3) * 2;
#pragma unroll
    for (int mt = 0; mt < 2; mt++) {
#pragma unroll
        for (int nt = 0; nt < 8; nt++) {
            int row = rowBase + warpM * 32 + mt * 16 + fr;
            int col = colBase + warpN * 64 + nt * 8 + c2;
            *(__half2*)&g_simh[(size_t)row * NV + col] =
                __floats2half2_rn(acc[mt][nt][0], acc[mt][nt][1]);
            *(__half2*)&g_simh[(size_t)(row + 8) * NV + col] =
                __floats2half2_rn(acc[mt][nt][2], acc[mt][nt][3]);
        }
    }

    // ---- mirror write (bx > by): float staging, convert at drain ----
    if (bx > by) {
#pragma unroll 1
        for (int half = 0; half < 2; half++) {
            __syncthreads();
            if (warpN == half) {
#pragma unroll
                for (int mt = 0; mt < 2; mt++) {
#pragma unroll
                    for (int nt = 0; nt < 8; nt++) {
                        int lr = warpM * 32 + mt * 16 + fr;
                        int lc = nt * 8 + c2;
                        sm[lc * TRS + lr]            = acc[mt][nt][0];
                        sm[(lc + 1) * TRS + lr]      = acc[mt][nt][1];
                        sm[lc * TRS + lr + 8]        = acc[mt][nt][2];
                        sm[(lc + 1) * TRS + lr + 8]  = acc[mt][nt][3];
                    }
                }
            }
            __syncthreads();
#pragma unroll
            for (int ii = 0; ii < 8; ii++) {
                int it = tid + ii * 256;
                int c = it >> 5;
                int g = it & 31;
                int j = colBase + half * 64 + c;
                float4 v = *(float4*)&sm[c * TRS + g * 4];
                __half2 lo = __floats2half2_rn(v.x, v.y);
                __half2 hi = __floats2half2_rn(v.z, v.w);
                uint2 pk = make_uint2(*(uint32_t*)&lo, *(uint32_t*)&hi);
                *(uint2*)&g_simh[(size_t)j * NV + rowBase + g * 4] = pk;
            }
        }
    }
}

// ============================================================================
// Phase 2: coarse tournament top-k with 32-bit keys + REDUX.MAX.U32.
// key = sameflag<<31 | ord16<<13 | (NV - j). removed = 1<<31.
// ============================================================================
__device__ __forceinline__ unsigned o16(unsigned u) {
    return (u & 0x8000u) ? (0xFFFFu & ~u) : (u | 0x8000u);
}
__device__ __forceinline__ unsigned f2ord(float f) {
    unsigned b = __float_as_uint(f);
    return (b & 0x80000000u) ? ~b : (b | 0x80000000u);
}

__global__ void __launch_bounds__(256) topk_kernel(const int* __restrict__ bid) {
    int i = blockIdx.x;
    int tid = threadIdx.x;
    int lane = tid & 31;
    int wid = tid >> 5;

    __shared__ unsigned keys[NV];      // 16 KB
    __shared__ unsigned cmax[NCHUNK];
    __shared__ int chosen[NC];

    int myb = __ldg(&bid[i]);

    const uint4* row16 = (const uint4*)&g_simh[(size_t)i * NV];   // 8 halves per uint4
    const int4*  bid4  = (const int4*)bid;
    for (int t = tid; t < NV / 8; t += 256) {
        uint4 w = __ldg(&row16[t]);
        int4 g1 = __ldg(&bid4[t * 2]);
        int4 g2 = __ldg(&bid4[t * 2 + 1]);
        int j0 = t * 8;
        unsigned h;
        h = w.x;
        keys[j0 + 0] = ((g1.x == myb) ? 0x80000000u : 0u) | (o16(h & 0xFFFFu) << 13) | (unsigned)(NV - (j0 + 0));
        keys[j0 + 1] = ((g1.y == myb) ? 0x80000000u : 0u) | (o16(h >> 16) << 13) | (unsigned)(NV - (j0 + 1));
        h = w.y;
        keys[j0 + 2] = ((g1.z == myb) ? 0x80000000u : 0u) | (o16(h & 0xFFFFu) << 13) | (unsigned)(NV - (j0 + 2));
        keys[j0 + 3] = ((g1.w == myb) ? 0x80000000u : 0u) | (o16(h >> 16) << 13) | (unsigned)(NV - (j0 + 3));
        h = w.z;
        keys[j0 + 4] = ((g2.x == myb) ? 0x80000000u : 0u) | (o16(h & 0xFFFFu) << 13) | (unsigned)(NV - (j0 + 4));
        keys[j0 + 5] = ((g2.y == myb) ? 0x80000000u : 0u) | (o16(h >> 16) << 13) | (unsigned)(NV - (j0 + 5));
        h = w.w;
        keys[j0 + 6] = ((g2.z == myb) ? 0x80000000u : 0u) | (o16(h & 0xFFFFu) << 13) | (unsigned)(NV - (j0 + 6));
        keys[j0 + 7] = ((g2.w == myb) ? 0x80000000u : 0u) | (o16(h >> 16) << 13) | (unsigned)(NV - (j0 + 7));
    }
    __syncthreads();

#pragma unroll 1
    for (int phase = 0; phase < 2; phase++) {
        unsigned xm = phase ? 0x80000000u : 0u;
        int cnt  = phase ? NE : NI;
        int base = phase ? NI : 0;

#pragma unroll
        for (int cc = 0; cc < 8; cc++) {
            int c = wid * 8 + cc;
            unsigned a = keys[c * 64 + lane] ^ xm;
            unsigned b = keys[c * 64 + 32 + lane] ^ xm;
            unsigned m = __reduce_max_sync(0xffffffffu, a > b ? a : b);
            if (lane == 0) cmax[c] = m;
        }
        __syncthreads();

        if (wid == 0) {
#pragma unroll 1
            for (int t = 0; t < cnt; t++) {
                unsigned a = cmax[lane];
                unsigned b = cmax[lane + 32];
                unsigned m = __reduce_max_sync(0xffffffffu, a > b ? a : b);
                int j = NV - (int)(m & 0x1FFFu);
                int c = j >> 6;
                if (lane == 0) {
                    chosen[base + t] = j;
                    keys[j] = 0x80000000u;     // removed: neutral both phases
                }
                __syncwarp();
                unsigned ra = keys[c * 64 + lane] ^ xm;
                unsigned rb = keys[c * 64 + 32 + lane] ^ xm;
                unsigned rm = __reduce_max_sync(0xffffffffu, ra > rb ? ra : rb);
                if (lane == 0) cmax[c] = rm;
                __syncwarp();
            }
        }
        __syncthreads();
    }

    if (tid < NC) g_cand[i * NC + tid] = chosen[tid];
}

// ============================================================================
// Phase 3: EXACT rescore (k-ascending sequential fmaf == reference chain).
// ============================================================================
__global__ void __launch_bounds__(256) rescore_kernel(const float* __restrict__ E) {
    int tid = threadIdx.x;
    int grp = tid >> 6;
    int sub = tid & 63;
    int row = blockIdx.x * 4 + grp;

    __shared__ float4 EiS[4][64];
    __shared__ int    candS[4][NC];
    __shared__ ull    keyS[4][NC];
    __shared__ int    knnS[4][NSEL];

    EiS[grp][sub] = __ldg((const float4*)&E[(size_t)row * DV] + sub);
    if (sub < NC) candS[grp][sub] = g_cand[row * NC + sub];
    __syncthreads();

    if (sub < NC) {
        int j = candS[grp][sub];
        const float4* Ej4 = (const float4*)&E[(size_t)j * DV];
        const float* Ei = (const float*)&EiS[grp][0];
        float acc = 0.0f;
#pragma unroll 4
        for (int k4 = 0; k4 < 64; k4++) {
            float4 b = __ldg(&Ej4[k4]);
            acc = fmaf(Ei[k4 * 4 + 0], b.x, acc);
            acc = fmaf(Ei[k4 * 4 + 1], b.y, acc);
            acc = fmaf(Ei[k4 * 4 + 2], b.z, acc);
            acc = fmaf(Ei[k4 * 4 + 3], b.w, acc);
        }
        keyS[grp][sub] = ((ull)f2ord(acc) << 13) | (unsigned)(NV - j);
    }
    __syncthreads();

    if (sub < NC) {
        int lo = (sub < NI) ? 0 : NI;
        int hi = (sub < NI) ? NI : NC;
        ull mykey = keyS[grp][sub];
        int r = 0;
        for (int u = lo; u < hi; u++)
            if (keyS[grp][u] > mykey) r++;
        int j = candS[grp][sub];
        if (sub < NI) {
            if (r >= 1 && r <= TK) knnS[grp][r - 1] = j;
        } else {
            if (r < TKI) knnS[grp][TK + r] = j;
        }
    }
    __syncthreads();

    if (sub < NSEL) g_knn[row * NSEL + sub] = knnS[grp][sub];

    unsigned b0 = 0, b1 = 0;
    int w0 = sub * 2;
#pragma unroll
    for (int t = 0; t < NSEL; t++) {
        int j = knnS[grp][t];
        int wi = j >> 5;
        unsigned bit = 1u << (j & 31);
        if (wi == w0) b0 |= bit;
        if (wi == w0 + 1) b1 |= bit;
    }
    g_bits[row * NW + w0] = b0;
    g_bits[row * NW + w0 + 1] = b1;
}

// ============================================================================
// Phase 4: mutual check -> scatter locality + all_close
// ============================================================================
__global__ void __launch_bounds__(256) finalize_kernel(
    const float* __restrict__ adj, const int* __restrict__ cl,
    float* __restrict__ out) {
    int id = blockIdx.x * blockDim.x + threadIdx.x;
    if (id >= NV * NSEL) return;
    int i = id / NSEL;
    int j = g_knn[id];

    bool mut = (j != i) && ((g_bits[j * NW + (i >> 5)] >> (i & 31)) & 1u);
    if (mut) out[(size_t)i * NV + j] = adj[(size_t)i * NV + j];

    bool ac = mut;
    if (!ac) {
        ac = true;
#pragma unroll
        for (int m = 0; m < MLAB; m++)
            if (cl[m * NV + i] != cl[m * NV + j]) ac = false;
    }
    out[(size_t)NV * NV + id] = ac ? 1.0f : 0.0f;
}

// ============================================================================
extern "C" void kernel_launch(void* const* d_in, const int* in_sizes, int n_in,
                              void* d_out, int out_size) {
    const float* adj = (const float*)d_in[0];
    const float* E   = (const float*)d_in[1];
    const int*   bid = (const int*)d_in[2];
    const int*   cl  = (const int*)d_in[3];
    float* out = (float*)d_out;

    cudaFuncSetAttribute(gemm_tf32_kernel, cudaFuncAttributeMaxDynamicSharedMemorySize,
                         GSMEM_BYTES);

    cudaMemsetAsync(out, 0, (size_t)NV * NV * sizeof(float));
    dim3 grid(NV / 128, NV / 128);
    gemm_tf32_kernel<<<grid, 256, GSMEM_BYTES>>>(E);
    topk_kernel<<<NV, 256>>>(bid);
    rescore_kernel<<<NV / 4, 256>>>(E);
    finalize_kernel<<<(NV * NSEL + 255) / 256, 256>>>(adj, cl, out);
}

// round 10
// speedup vs baseline: 1.4193x; 1.0158x over previous
#include <cuda_runtime.h>
#include <cuda_fp16.h>
#include <cstdint>
#include <math_constants.h>

#define NV   4096
#define DV   256
#define TK   20
#define TKI  10
#define NSEL 30
#define MLAB 5
#define NW   (NV/32)
#define NI   26          // coarse intra candidates (incl self)
#define NE   14          // coarse inter candidates
#define NC   (NI + NE)   // 40
#define FB   (1u << 28)  // flag bit position inside 32-bit scan key

typedef unsigned long long ull;

// -------- scratch (static device globals; no allocation) --------
__device__ unsigned short g_p16[(size_t)NV * NV];  // 32 MB packed coarse keys
__device__ int      g_cand[NV * NC];
__device__ int      g_knn[NV * NSEL];
__device__ unsigned g_bits[NV * NW];

// ============================================================================
// Phase 1: coarse sim via single-term tf32 mma.sync; epilogue packs
// p = sameflag<<15 | o15(fp16(v)) and writes 16-bit keys (direct + mirror).
// ============================================================================
#define SLS 136
#define SLAB (32 * SLS)
#define GSMEM_FLOATS (2 * SLAB)        // A0, B0
#define GSMEM_BYTES (GSMEM_FLOATS * 4) // 34816 B
#define STS2 136                       // ushort mirror staging stride (136*2=272=16*17)

__device__ __forceinline__ uint32_t tf32of(float x) {
    uint32_t u;
    asm("cvt.rna.tf32.f32 %0, %1;" : "=r"(u) : "f"(x));
    return u;
}
__device__ __forceinline__ uint32_t fbits(float x) { return __float_as_uint(x); }

__device__ __forceinline__ void mma_tf32(float d[4], const uint32_t a[4],
                                         uint32_t b0, uint32_t b1) {
    asm volatile(
        "mma.sync.aligned.m16n8k8.row.col.f32.tf32.tf32.f32 "
        "{%0,%1,%2,%3}, {%4,%5,%6,%7}, {%8,%9}, {%0,%1,%2,%3};"
        : "+f"(d[0]), "+f"(d[1]), "+f"(d[2]), "+f"(d[3])
        : "r"(a[0]), "r"(a[1]), "r"(a[2]), "r"(a[3]), "r"(b0), "r"(b1));
}

__device__ __forceinline__ unsigned pack_p(float v, bool same) {
    unsigned u = __half_as_ushort(__float2half_rn(v));
    unsigned o = (u & 0x8000u) ? ((~u) & 0xFFFFu) : (u | 0x8000u);
    return (same ? 0x8000u : 0u) | (o >> 1);
}

__global__ void __launch_bounds__(256, 2) gemm_tf32_kernel(const float* __restrict__ E,
                                                           const int* __restrict__ bid) {
    int bx = blockIdx.x;
    int by = blockIdx.y;
    if (bx < by) return;

    extern __shared__ float sm[];
    float* A0 = sm;
    float* B0 = sm + SLAB;

    int tid = threadIdx.x;
    int lane = tid & 31;
    int wid = tid >> 5;
    int warpM = wid & 3;
    int warpN = wid >> 2;

    int rowBase = by * 128;
    int colBase = bx * 128;

    float acc[2][8][4];
#pragma unroll
    for (int mt = 0; mt < 2; mt++)
#pragma unroll
        for (int nt = 0; nt < 8; nt++)
#pragma unroll
            for (int g = 0; g < 4; g++) acc[mt][nt][g] = 0.0f;

    int fr = lane >> 2;
    int fc = lane & 3;

#pragma unroll 1
    for (int chunk = 0; chunk < 8; chunk++) {
        int k0 = chunk * 32;
#pragma unroll
        for (int ii = 0; ii < 4; ii++) {
            int it = tid + ii * 256;
            int r = it >> 3;
            int c4 = (it & 7) * 4;
            float4 va = __ldg((const float4*)&E[(size_t)(rowBase + r) * DV + k0 + c4]);
            float4 vb = __ldg((const float4*)&E[(size_t)(colBase + r) * DV + k0 + c4]);
            float ax[4] = {va.x, va.y, va.z, va.w};
            float bxv[4] = {vb.x, vb.y, vb.z, vb.w};
#pragma unroll
            for (int j = 0; j < 4; j++) {
                int kk = c4 + j;
                A0[kk * SLS + r] = __uint_as_float(tf32of(ax[j]));
                B0[kk * SLS + r] = __uint_as_float(tf32of(bxv[j]));
            }
        }
        __syncthreads();

#pragma unroll
        for (int ks = 0; ks < 4; ks++) {
            int kk = ks * 8;
            uint32_t aF[2][4];
#pragma unroll
            for (int mt = 0; mt < 2; mt++) {
                int m = warpM * 32 + mt * 16;
                aF[mt][0] = fbits(A0[(kk + fc) * SLS + m + fr]);
                aF[mt][1] = fbits(A0[(kk + fc) * SLS + m + fr + 8]);
                aF[mt][2] = fbits(A0[(kk + fc + 4) * SLS + m + fr]);
                aF[mt][3] = fbits(A0[(kk + fc + 4) * SLS + m + fr + 8]);
            }
#pragma unroll
            for (int nt = 0; nt < 8; nt++) {
                int n = warpN * 64 + nt * 8 + fr;
                uint32_t b0 = fbits(B0[(kk + fc) * SLS + n]);
                uint32_t b1 = fbits(B0[(kk + fc + 4) * SLS + n]);
#pragma unroll
                for (int mt = 0; mt < 2; mt++)
                    mma_tf32(acc[mt][nt], aF[mt], b0, b1);
            }
        }
        __syncthreads();
    }

    // ---- direct write: packed 16-bit keys (covers diag tile fully) ----
    int c2 = (lane & 3) * 2;
#pragma unroll
    for (int mt = 0; mt < 2; mt++) {
        int row = rowBase + warpM * 32 + mt * 16 + fr;
        int br0 = __ldg(&bid[row]);
        int br1 = __ldg(&bid[row + 8]);
#pragma unroll
        for (int nt = 0; nt < 8; nt++) {
            int col = colBase + warpN * 64 + nt * 8 + c2;
            int bc0 = __ldg(&bid[col]);
            int bc1 = __ldg(&bid[col + 1]);
            unsigned p00 = pack_p(acc[mt][nt][0], bc0 == br0);
            unsigned p01 = pack_p(acc[mt][nt][1], bc1 == br0);
            unsigned p10 = pack_p(acc[mt][nt][2], bc0 == br1);
            unsigned p11 = pack_p(acc[mt][nt][3], bc1 == br1);
            *(uint32_t*)&g_p16[(size_t)row * NV + col] = p00 | (p01 << 16);
            *(uint32_t*)&g_p16[(size_t)(row + 8) * NV + col] = p10 | (p11 << 16);
        }
    }

    // ---- mirror write (bx > by): stage packed keys (flag/value symmetric) ----
    if (bx > by) {
        unsigned short* smT = (unsigned short*)sm;
#pragma unroll 1
        for (int half = 0; half < 2; half++) {
            __syncthreads();
            if (warpN == half) {
#pragma unroll
                for (int mt = 0; mt < 2; mt++) {
                    int row = rowBase + warpM * 32 + mt * 16 + fr;
                    int br0 = __ldg(&bid[row]);
                    int br1 = __ldg(&bid[row + 8]);
                    int lr = warpM * 32 + mt * 16 + fr;
#pragma unroll
                    for (int nt = 0; nt < 8; nt++) {
                        int col = colBase + half * 64 + nt * 8 + c2;
                        int bc0 = __ldg(&bid[col]);
                        int bc1 = __ldg(&bid[col + 1]);
                        int lc = nt * 8 + c2;
                        smT[lc * STS2 + lr]           = (unsigned short)pack_p(acc[mt][nt][0], bc0 == br0);
                        smT[(lc + 1) * STS2 + lr]     = (unsigned short)pack_p(acc[mt][nt][1], bc1 == br0);
                        smT[lc * STS2 + lr + 8]       = (unsigned short)pack_p(acc[mt][nt][2], bc0 == br1);
                        smT[(lc + 1) * STS2 + lr + 8] = (unsigned short)pack_p(acc[mt][nt][3], bc1 == br1);
                    }
                }
            }
            __syncthreads();
#pragma unroll
            for (int ii = 0; ii < 4; ii++) {
                int it = tid + ii * 256;     // 0..1023
                int c = it >> 4;             // 0..63
                int g = it & 15;             // 0..15
                int j = colBase + half * 64 + c;
                uint4 v = *(uint4*)&smT[c * STS2 + g * 8];
                *(uint4*)&g_p16[(size_t)j * NV + rowBase + g * 8] = v;
            }
        }
    }
}

// ============================================================================
// Phase 2: coarse tournament top-k. smem = raw 16-bit packed keys (8 KB);
// 32-bit scan key = (p<<13) | (NV - j) built in registers.
// Single pass computes BOTH phases' chunk maxima. removed: p = 0x8000.
// ============================================================================
__device__ __forceinline__ unsigned f2ord(float f) {
    unsigned b = __float_as_uint(f);
    return (b & 0x80000000u) ? ~b : (b | 0x80000000u);
}

__global__ void __launch_bounds__(256) topk_kernel() {
    int i = blockIdx.x;
    int tid = threadIdx.x;
    int lane = tid & 31;
    int wid = tid >> 5;

    __shared__ unsigned short sp[NV];      // 8 KB
    __shared__ unsigned cm0[64], cm1[64];
    __shared__ int chosen[NC];

    const uint4* row = (const uint4*)&g_p16[(size_t)i * NV];
    for (int t = tid; t < NV / 8; t += 256) ((uint4*)sp)[t] = __ldg(&row[t]);
    __syncthreads();

    // dual-phase chunk maxima in one pass
#pragma unroll
    for (int cc = 0; cc < 8; cc++) {
        int c = wid * 8 + cc;
        int j1 = c * 64 + lane;
        int j2 = j1 + 32;
        unsigned k1 = ((unsigned)sp[j1] << 13) | (unsigned)(NV - j1);
        unsigned k2 = ((unsigned)sp[j2] << 13) | (unsigned)(NV - j2);
        unsigned m0 = __reduce_max_sync(0xffffffffu, k1 > k2 ? k1 : k2);
        unsigned x1 = k1 ^ FB, x2 = k2 ^ FB;
        unsigned m1 = __reduce_max_sync(0xffffffffu, x1 > x2 ? x1 : x2);
        if (lane == 0) { cm0[c] = m0; cm1[c] = m1; }
    }
    __syncthreads();

    if (wid == 0) {
#pragma unroll 1
        for (int phase = 0; phase < 2; phase++) {
            unsigned* cm = phase ? cm1 : cm0;
            unsigned xm = phase ? FB : 0u;
            int cnt  = phase ? NE : NI;
            int base = phase ? NI : 0;
#pragma unroll 1
            for (int t = 0; t < cnt; t++) {
                unsigned a = cm[lane];
                unsigned b = cm[lane + 32];
                unsigned m = __reduce_max_sync(0xffffffffu, a > b ? a : b);
                int j = NV - (int)(m & 0x1FFFu);
                int c = j >> 6;
                if (lane == 0) {
                    chosen[base + t] = j;
                    sp[j] = 0x8000;          // neutral in both orderings
                }
                __syncwarp();
                int j1 = c * 64 + lane;
                int j2 = j1 + 32;
                unsigned k1 = (((unsigned)sp[j1] << 13) | (unsigned)(NV - j1)) ^ xm;
                unsigned k2 = (((unsigned)sp[j2] << 13) | (unsigned)(NV - j2)) ^ xm;
                unsigned rm = __reduce_max_sync(0xffffffffu, k1 > k2 ? k1 : k2);
                if (lane == 0) cm[c] = rm;
                __syncwarp();
            }
        }
    }
    __syncthreads();

    if (tid < NC) g_cand[i * NC + tid] = chosen[tid];
}

// ============================================================================
// Phase 3: EXACT rescore (k-ascending sequential fmaf == reference chain).
// ============================================================================
__global__ void __launch_bounds__(256) rescore_kernel(const float* __restrict__ E) {
    int tid = threadIdx.x;
    int grp = tid >> 6;
    int sub = tid & 63;
    int row = blockIdx.x * 4 + grp;

    __shared__ float4 EiS[4][64];
    __shared__ int    candS[4][NC];
    __shared__ ull    keyS[4][NC];
    __shared__ int    knnS[4][NSEL];

    EiS[grp][sub] = __ldg((const float4*)&E[(size_t)row * DV] + sub);
    if (sub < NC) candS[grp][sub] = g_cand[row * NC + sub];
    __syncthreads();

    if (sub < NC) {
        int j = candS[grp][sub];
        const float4* Ej4 = (const float4*)&E[(size_t)j * DV];
        const float* Ei = (const float*)&EiS[grp][0];
        float acc = 0.0f;
#pragma unroll 4
        for (int k4 = 0; k4 < 64; k4++) {
            float4 b = __ldg(&Ej4[k4]);
            acc = fmaf(Ei[k4 * 4 + 0], b.x, acc);
            acc = fmaf(Ei[k4 * 4 + 1], b.y, acc);
            acc = fmaf(Ei[k4 * 4 + 2], b.z, acc);
            acc = fmaf(Ei[k4 * 4 + 3], b.w, acc);
        }
        keyS[grp][sub] = ((ull)f2ord(acc) << 13) | (unsigned)(NV - j);
    }
    __syncthreads();

    if (sub < NC) {
        int lo = (sub < NI) ? 0 : NI;
        int hi = (sub < NI) ? NI : NC;
        ull mykey = keyS[grp][sub];
        int r = 0;
        for (int u = lo; u < hi; u++)
            if (keyS[grp][u] > mykey) r++;
        int j = candS[grp][sub];
        if (sub < NI) {
            if (r >= 1 && r <= TK) knnS[grp][r - 1] = j;
        } else {
            if (r < TKI) knnS[grp][TK + r] = j;
        }
    }
    __syncthreads();

    if (sub < NSEL) g_knn[row * NSEL + sub] = knnS[grp][sub];

    unsigned b0 = 0, b1 = 0;
    int w0 = sub * 2;
#pragma unroll
    for (int t = 0; t < NSEL; t++) {
        int j = knnS[grp][t];
        int wi = j >> 5;
        unsigned bit = 1u << (j & 31);
        if (wi == w0) b0 |= bit;
        if (wi == w0 + 1) b1 |= bit;
    }
    g_bits[row * NW + w0] = b0;
    g_bits[row * NW + w0 + 1] = b1;
}

// ============================================================================
// Phase 4: mutual check -> scatter locality + all_close
// ============================================================================
__global__ void __launch_bounds__(256) finalize_kernel(
    const float* __restrict__ adj, const int* __restrict__ cl,
    float* __restrict__ out) {
    int id = blockIdx.x * blockDim.x + threadIdx.x;
    if (id >= NV * NSEL) return;
    int i = id / NSEL;
    int j = g_knn[id];

    bool mut = (j != i) && ((g_bits[j * NW + (i >> 5)] >> (i & 31)) & 1u);
    if (mut) out[(size_t)i * NV + j] = adj[(size_t)i * NV + j];

    bool ac = mut;
    if (!ac) {
        ac = true;
#pragma unroll
        for (int m = 0; m < MLAB; m++)
            if (cl[m * NV + i] != cl[m * NV + j]) ac = false;
    }
    out[(size_t)NV * NV + id] = ac ? 1.0f : 0.0f;
}

// ============================================================================
extern "C" void kernel_launch(void* const* d_in, const int* in_sizes, int n_in,
                              void* d_out, int out_size) {
    const float* adj = (const float*)d_in[0];
    const float* E   = (const float*)d_in[1];
    const int*   bid = (const int*)d_in[2];
    const int*   cl  = (const int*)d_in[3];
    float* out = (float*)d_out;

    cudaFuncSetAttribute(gemm_tf32_kernel, cudaFuncAttributeMaxDynamicSharedMemorySize,
                         GSMEM_BYTES);

    cudaMemsetAsync(out, 0, (size_t)NV * NV * sizeof(float));
    dim3 grid(NV / 128, NV / 128);
    gemm_tf32_kernel<<<grid, 256, GSMEM_BYTES>>>(E, bid);
    topk_kernel<<<NV, 256>>>();
    rescore_kernel<<<NV / 4, 256>>>(E);
    finalize_kernel<<<(NV * NSEL + 255) / 256, 256>>>(adj, cl, out);
}

// round 11
// speedup vs baseline: 1.4418x; 1.0158x over previous
#include <cuda_runtime.h>
#include <cuda_fp16.h>
#include <cstdint>
#include <math_constants.h>

#define NV   4096
#define DV   256
#define TK   20
#define TKI  10
#define NSEL 30
#define MLAB 5
#define NW   (NV/32)
#define NI   26
#define NE   14
#define NC   (NI + NE)
#define FB   (1u << 28)

typedef unsigned long long ull;

// -------- scratch (static device globals; no allocation) --------
__device__ unsigned short g_p16[(size_t)NV * NV];  // 32 MB packed coarse keys
__device__ int      g_cand[NV * NC];
__device__ int      g_knn[NV * NSEL];
__device__ unsigned g_bits[NV * NW];

// ============================================================================
// Phase 1: coarse sim via tf32 mma.sync. Row-major smem slabs (NO transpose),
// float4 STS, conflict-free fragment LDS, double-buffered chunk pipeline.
// Epilogue packs p = sameflag<<15 | o15(fp16(v)); direct + mirror writes.
// ============================================================================
#define ASTR 36                         // slab row stride in floats (div by 4)
#define SLABF (128 * ASTR)              // one slab: 128 rows x 32 k
#define GSMEM_BYTES (4 * SLABF * 4)     // A[2], B[2] = 73728 B
#define STS2 136                        // ushort mirror staging stride

__device__ __forceinline__ uint32_t tf32of(float x) {
    uint32_t u;
    asm("cvt.rna.tf32.f32 %0, %1;" : "=r"(u) : "f"(x));
    return u;
}
__device__ __forceinline__ uint32_t fbits(float x) { return __float_as_uint(x); }

__device__ __forceinline__ void mma_tf32(float d[4], const uint32_t a[4],
                                         uint32_t b0, uint32_t b1) {
    asm volatile(
        "mma.sync.aligned.m16n8k8.row.col.f32.tf32.tf32.f32 "
        "{%0,%1,%2,%3}, {%4,%5,%6,%7}, {%8,%9}, {%0,%1,%2,%3};"
        : "+f"(d[0]), "+f"(d[1]), "+f"(d[2]), "+f"(d[3])
        : "r"(a[0]), "r"(a[1]), "r"(a[2]), "r"(a[3]), "r"(b0), "r"(b1));
}

__device__ __forceinline__ unsigned pack_p(float v, bool same) {
    unsigned u = __half_as_ushort(__float2half_rn(v));
    unsigned o = (u & 0x8000u) ? ((~u) & 0xFFFFu) : (u | 0x8000u);
    return (same ? 0x8000u : 0u) | (o >> 1);
}

__device__ __forceinline__ float4 tf32x4(float4 v) {
    return make_float4(__uint_as_float(tf32of(v.x)), __uint_as_float(tf32of(v.y)),
                       __uint_as_float(tf32of(v.z)), __uint_as_float(tf32of(v.w)));
}

__global__ void __launch_bounds__(256, 2) gemm_tf32_kernel(const float* __restrict__ E,
                                                           const int* __restrict__ bid) {
    int bx = blockIdx.x;
    int by = blockIdx.y;
    if (bx < by) return;

    extern __shared__ float sm[];
    float* As[2] = {sm, sm + SLABF};
    float* Bs[2] = {sm + 2 * SLABF, sm + 3 * SLABF};

    int tid = threadIdx.x;
    int lane = tid & 31;
    int wid = tid >> 5;
    int warpM = wid & 3;
    int warpN = wid >> 2;

    int rowBase = by * 128;
    int colBase = bx * 128;

    float acc[2][8][4];
#pragma unroll
    for (int mt = 0; mt < 2; mt++)
#pragma unroll
        for (int nt = 0; nt < 8; nt++)
#pragma unroll
            for (int g = 0; g < 4; g++) acc[mt][nt][g] = 0.0f;

    int fr = lane >> 2;
    int fc = lane & 3;

    // loader mapping: 2 threads per row, 16 floats each
    int lr = tid >> 1;
    int lq = (tid & 1) * 16;
    const float4* gA = (const float4*)&E[(size_t)(rowBase + lr) * DV + lq];
    const float4* gB = (const float4*)&E[(size_t)(colBase + lr) * DV + lq];

    float4 pa[4], pb[4];
#pragma unroll
    for (int q = 0; q < 4; q++) { pa[q] = __ldg(gA + q); pb[q] = __ldg(gB + q); }

#pragma unroll 1
    for (int chunk = 0; chunk < 8; chunk++) {
        int buf = chunk & 1;
        // store current chunk (tf32-converted, float4 STS)
        float* Aw = As[buf];
        float* Bw = Bs[buf];
#pragma unroll
        for (int q = 0; q < 4; q++) {
            *(float4*)&Aw[lr * ASTR + lq + q * 4] = tf32x4(pa[q]);
            *(float4*)&Bw[lr * ASTR + lq + q * 4] = tf32x4(pb[q]);
        }
        __syncthreads();

        // prefetch next chunk
        if (chunk < 7) {
            int koff = (chunk + 1) * 8;   // in float4 units
#pragma unroll
            for (int q = 0; q < 4; q++) {
                pa[q] = __ldg(gA + koff + q);
                pb[q] = __ldg(gB + koff + q);
            }
        }

        // compute on buf
        const float* Ar = As[buf];
        const float* Br = Bs[buf];
#pragma unroll
        for (int ks = 0; ks < 4; ks++) {
            int kk = ks * 8;
            uint32_t aF[2][4];
#pragma unroll
            for (int mt = 0; mt < 2; mt++) {
                int m = warpM * 32 + mt * 16;
                aF[mt][0] = fbits(Ar[(m + fr) * ASTR + kk + fc]);
                aF[mt][1] = fbits(Ar[(m + fr + 8) * ASTR + kk + fc]);
                aF[mt][2] = fbits(Ar[(m + fr) * ASTR + kk + fc + 4]);
                aF[mt][3] = fbits(Ar[(m + fr + 8) * ASTR + kk + fc + 4]);
            }
#pragma unroll
            for (int nt = 0; nt < 8; nt++) {
                int n = warpN * 64 + nt * 8 + fr;
                uint32_t b0 = fbits(Br[n * ASTR + kk + fc]);
                uint32_t b1 = fbits(Br[n * ASTR + kk + fc + 4]);
#pragma unroll
                for (int mt = 0; mt < 2; mt++)
                    mma_tf32(acc[mt][nt], aF[mt], b0, b1);
            }
        }
        __syncthreads();
    }

    // ---- direct write: packed 16-bit keys (covers diag tile fully) ----
    int c2 = (lane & 3) * 2;
#pragma unroll
    for (int mt = 0; mt < 2; mt++) {
        int row = rowBase + warpM * 32 + mt * 16 + fr;
        int br0 = __ldg(&bid[row]);
        int br1 = __ldg(&bid[row + 8]);
#pragma unroll
        for (int nt = 0; nt < 8; nt++) {
            int col = colBase + warpN * 64 + nt * 8 + c2;
            int bc0 = __ldg(&bid[col]);
            int bc1 = __ldg(&bid[col + 1]);
            unsigned p00 = pack_p(acc[mt][nt][0], bc0 == br0);
            unsigned p01 = pack_p(acc[mt][nt][1], bc1 == br0);
            unsigned p10 = pack_p(acc[mt][nt][2], bc0 == br1);
            unsigned p11 = pack_p(acc[mt][nt][3], bc1 == br1);
            *(uint32_t*)&g_p16[(size_t)row * NV + col] = p00 | (p01 << 16);
            *(uint32_t*)&g_p16[(size_t)(row + 8) * NV + col] = p10 | (p11 << 16);
        }
    }

    // ---- mirror write (bx > by): stage packed keys (flag/value symmetric) ----
    if (bx > by) {
        unsigned short* smT = (unsigned short*)sm;
#pragma unroll 1
        for (int half = 0; half < 2; half++) {
            __syncthreads();
            if (warpN == half) {
#pragma unroll
                for (int mt = 0; mt < 2; mt++) {
                    int row = rowBase + warpM * 32 + mt * 16 + fr;
                    int br0 = __ldg(&bid[row]);
                    int br1 = __ldg(&bid[row + 8]);
                    int lrr = warpM * 32 + mt * 16 + fr;
#pragma unroll
                    for (int nt = 0; nt < 8; nt++) {
                        int col = colBase + half * 64 + nt * 8 + c2;
                        int bc0 = __ldg(&bid[col]);
                        int bc1 = __ldg(&bid[col + 1]);
                        int lc = nt * 8 + c2;
                        smT[lc * STS2 + lrr]           = (unsigned short)pack_p(acc[mt][nt][0], bc0 == br0);
                        smT[(lc + 1) * STS2 + lrr]     = (unsigned short)pack_p(acc[mt][nt][1], bc1 == br0);
                        smT[lc * STS2 + lrr + 8]       = (unsigned short)pack_p(acc[mt][nt][2], bc0 == br1);
                        smT[(lc + 1) * STS2 + lrr + 8] = (unsigned short)pack_p(acc[mt][nt][3], bc1 == br1);
                    }
                }
            }
            __syncthreads();
#pragma unroll
            for (int ii = 0; ii < 4; ii++) {
                int it = tid + ii * 256;
                int c = it >> 4;
                int g = it & 15;
                int j = colBase + half * 64 + c;
                uint4 v = *(uint4*)&smT[c * STS2 + g * 8];
                *(uint4*)&g_p16[(size_t)j * NV + rowBase + g * 8] = v;
            }
        }
    }
}

// ============================================================================
// Phase 2: coarse tournament top-k on packed 16-bit keys (unchanged from R10)
// ============================================================================
__device__ __forceinline__ unsigned f2ord(float f) {
    unsigned b = __float_as_uint(f);
    return (b & 0x80000000u) ? ~b : (b | 0x80000000u);
}

__global__ void __launch_bounds__(256) topk_kernel() {
    int i = blockIdx.x;
    int tid = threadIdx.x;
    int lane = tid & 31;
    int wid = tid >> 5;

    __shared__ unsigned short sp[NV];
    __shared__ unsigned cm0[64], cm1[64];
    __shared__ int chosen[NC];

    const uint4* row = (const uint4*)&g_p16[(size_t)i * NV];
    for (int t = tid; t < NV / 8; t += 256) ((uint4*)sp)[t] = __ldg(&row[t]);
    __syncthreads();

#pragma unroll
    for (int cc = 0; cc < 8; cc++) {
        int c = wid * 8 + cc;
        int j1 = c * 64 + lane;
        int j2 = j1 + 32;
        unsigned k1 = ((unsigned)sp[j1] << 13) | (unsigned)(NV - j1);
        unsigned k2 = ((unsigned)sp[j2] << 13) | (unsigned)(NV - j2);
        unsigned m0 = __reduce_max_sync(0xffffffffu, k1 > k2 ? k1 : k2);
        unsigned x1 = k1 ^ FB, x2 = k2 ^ FB;
        unsigned m1 = __reduce_max_sync(0xffffffffu, x1 > x2 ? x1 : x2);
        if (lane == 0) { cm0[c] = m0; cm1[c] = m1; }
    }
    __syncthreads();

    if (wid == 0) {
#pragma unroll 1
        for (int phase = 0; phase < 2; phase++) {
            unsigned* cm = phase ? cm1 : cm0;
            unsigned xm = phase ? FB : 0u;
            int cnt  = phase ? NE : NI;
            int base = phase ? NI : 0;
#pragma unroll 1
            for (int t = 0; t < cnt; t++) {
                unsigned a = cm[lane];
                unsigned b = cm[lane + 32];
                unsigned m = __reduce_max_sync(0xffffffffu, a > b ? a : b);
                int j = NV - (int)(m & 0x1FFFu);
                int c = j >> 6;
                if (lane == 0) {
                    chosen[base + t] = j;
                    sp[j] = 0x8000;
                }
                __syncwarp();
                int j1 = c * 64 + lane;
                int j2 = j1 + 32;
                unsigned k1 = (((unsigned)sp[j1] << 13) | (unsigned)(NV - j1)) ^ xm;
                unsigned k2 = (((unsigned)sp[j2] << 13) | (unsigned)(NV - j2)) ^ xm;
                unsigned rm = __reduce_max_sync(0xffffffffu, k1 > k2 ? k1 : k2);
                if (lane == 0) cm[c] = rm;
                __syncwarp();
            }
        }
    }
    __syncthreads();

    if (tid < NC) g_cand[i * NC + tid] = chosen[tid];
}

// ============================================================================
// Phase 3: EXACT rescore (k-ascending sequential fmaf == reference chain).
// ============================================================================
__global__ void __launch_bounds__(256) rescore_kernel(const float* __restrict__ E) {
    int tid = threadIdx.x;
    int grp = tid >> 6;
    int sub = tid & 63;
    int row = blockIdx.x * 4 + grp;

    __shared__ float4 EiS[4][64];
    __shared__ int    candS[4][NC];
    __shared__ ull    keyS[4][NC];
    __shared__ int    knnS[4][NSEL];

    EiS[grp][sub] = __ldg((const float4*)&E[(size_t)row * DV] + sub);
    if (sub < NC) candS[grp][sub] = g_cand[row * NC + sub];
    __syncthreads();

    if (sub < NC) {
        int j = candS[grp][sub];
        const float4* Ej4 = (const float4*)&E[(size_t)j * DV];
        const float* Ei = (const float*)&EiS[grp][0];
        float acc = 0.0f;
#pragma unroll 4
        for (int k4 = 0; k4 < 64; k4++) {
            float4 b = __ldg(&Ej4[k4]);
            acc = fmaf(Ei[k4 * 4 + 0], b.x, acc);
            acc = fmaf(Ei[k4 * 4 + 1], b.y, acc);
            acc = fmaf(Ei[k4 * 4 + 2], b.z, acc);
            acc = fmaf(Ei[k4 * 4 + 3], b.w, acc);
        }
        keyS[grp][sub] = ((ull)f2ord(acc) << 13) | (unsigned)(NV - j);
    }
    __syncthreads();

    if (sub < NC) {
        int lo = (sub < NI) ? 0 : NI;
        int hi = (sub < NI) ? NI : NC;
        ull mykey = keyS[grp][sub];
        int r = 0;
        for (int u = lo; u < hi; u++)
            if (keyS[grp][u] > mykey) r++;
        int j = candS[grp][sub];
        if (sub < NI) {
            if (r >= 1 && r <= TK) knnS[grp][r - 1] = j;
        } else {
            if (r < TKI) knnS[grp][TK + r] = j;
        }
    }
    __syncthreads();

    if (sub < NSEL) g_knn[row * NSEL + sub] = knnS[grp][sub];

    unsigned b0 = 0, b1 = 0;
    int w0 = sub * 2;
#pragma unroll
    for (int t = 0; t < NSEL; t++) {
        int j = knnS[grp][t];
        int wi = j >> 5;
        unsigned bit = 1u << (j & 31);
        if (wi == w0) b0 |= bit;
        if (wi == w0 + 1) b1 |= bit;
    }
    g_bits[row * NW + w0] = b0;
    g_bits[row * NW + w0 + 1] = b1;
}

// ============================================================================
// Phase 4: mutual check -> scatter locality + all_close
// ============================================================================
__global__ void __launch_bounds__(256) finalize_kernel(
    const float* __restrict__ adj, const int* __restrict__ cl,
    float* __restrict__ out) {
    int id = blockIdx.x * blockDim.x + threadIdx.x;
    if (id >= NV * NSEL) return;
    int i = id / NSEL;
    int j = g_knn[id];

    bool mut = (j != i) && ((g_bits[j * NW + (i >> 5)] >> (i & 31)) & 1u);
    if (mut) out[(size_t)i * NV + j] = adj[(size_t)i * NV + j];

    bool ac = mut;
    if (!ac) {
        ac = true;
#pragma unroll
        for (int m = 0; m < MLAB; m++)
            if (cl[m * NV + i] != cl[m * NV + j]) ac = false;
    }
    out[(size_t)NV * NV + id] = ac ? 1.0f : 0.0f;
}

// ============================================================================
extern "C" void kernel_launch(void* const* d_in, const int* in_sizes, int n_in,
                              void* d_out, int out_size) {
    const float* adj = (const float*)d_in[0];
    const float* E   = (const float*)d_in[1];
    const int*   bid = (const int*)d_in[2];
    const int*   cl  = (const int*)d_in[3];
    float* out = (float*)d_out;

    cudaFuncSetAttribute(gemm_tf32_kernel, cudaFuncAttributeMaxDynamicSharedMemorySize,
                         GSMEM_BYTES);

    cudaMemsetAsync(out, 0, (size_t)NV * NV * sizeof(float));
    dim3 grid(NV / 128, NV / 128);
    gemm_tf32_kernel<<<grid, 256, GSMEM_BYTES>>>(E, bid);
    topk_kernel<<<NV, 256>>>();
    rescore_kernel<<<NV / 4, 256>>>(E);
    finalize_kernel<<<(NV * NSEL + 255) / 256, 256>>>(adj, cl, out);
}

// round 12
// speedup vs baseline: 1.6801x; 1.1653x over previous
#include <cuda_runtime.h>
#include <cuda_fp16.h>
#include <cstdint>
#include <math_constants.h>

#define NV   4096
#define DV   256
#define TK   20
#define TKI  10
#define NSEL 30
#define MLAB 5
#define NW   (NV/32)
#define NI   26
#define NE   14
#define NC   (NI + NE)
#define FB   (1u << 28)

typedef unsigned long long ull;

// -------- scratch (static device globals; no allocation) --------
__device__ unsigned short g_p16[(size_t)NV * NV];  // 32 MB packed coarse keys
__device__ int      g_cand[NV * NC];
__device__ int      g_knn[NV * NSEL];
__device__ unsigned g_bits[NV * NW];

// ============================================================================
// Phase 1: coarse sim via fp16 mma.sync m16n8k16 (half the MMA ops of tf32-k8).
// fp16 smem slabs, stride 40 halves (conflict-free fragment LDS),
// double-buffered 32-k chunks. Epilogue packs 16-bit keys; direct + mirror.
// ============================================================================
#define SL2 40                          // slab row stride in halves
#define SLABH (128 * SL2)               // halves per slab
#define GSMEM_BYTES (4 * SLABH * 2)     // A[2], B[2] fp16 = 40960 B
#define STS2 136                        // ushort mirror staging stride

__device__ __forceinline__ uint32_t h2u(__half2 h) { return *(uint32_t*)&h; }

__device__ __forceinline__ void mma_f16(float d[4], uint32_t a0, uint32_t a1,
                                        uint32_t a2, uint32_t a3,
                                        uint32_t b0, uint32_t b1) {
    asm volatile(
        "mma.sync.aligned.m16n8k16.row.col.f32.f16.f16.f32 "
        "{%0,%1,%2,%3}, {%4,%5,%6,%7}, {%8,%9}, {%0,%1,%2,%3};"
        : "+f"(d[0]), "+f"(d[1]), "+f"(d[2]), "+f"(d[3])
        : "r"(a0), "r"(a1), "r"(a2), "r"(a3), "r"(b0), "r"(b1));
}

__device__ __forceinline__ unsigned pack_p(float v, bool same) {
    unsigned u = __half_as_ushort(__float2half_rn(v));
    unsigned o = (u & 0x8000u) ? ((~u) & 0xFFFFu) : (u | 0x8000u);
    return (same ? 0x8000u : 0u) | (o >> 1);
}

__global__ void __launch_bounds__(256, 2) gemm_f16_kernel(const float* __restrict__ E,
                                                          const int* __restrict__ bid) {
    int bx = blockIdx.x;
    int by = blockIdx.y;
    if (bx < by) return;

    extern __shared__ __align__(16) unsigned short smh[];
    unsigned short* As[2] = {smh, smh + SLABH};
    unsigned short* Bs[2] = {smh + 2 * SLABH, smh + 3 * SLABH};

    int tid = threadIdx.x;
    int lane = tid & 31;
    int wid = tid >> 5;
    int warpM = wid & 3;
    int warpN = wid >> 2;

    int rowBase = by * 128;
    int colBase = bx * 128;

    float acc[2][8][4];
#pragma unroll
    for (int mt = 0; mt < 2; mt++)
#pragma unroll
        for (int nt = 0; nt < 8; nt++)
#pragma unroll
            for (int g = 0; g < 4; g++) acc[mt][nt][g] = 0.0f;

    int fr = lane >> 2;
    int fc = lane & 3;

    // loader: 2 threads per row, 16 floats (=16 halves) each per 32-k chunk
    int lr = tid >> 1;
    int lq4 = (tid & 1) * 4;   // float4 offset within chunk
    const float4* gA = (const float4*)&E[(size_t)(rowBase + lr) * DV] + lq4;
    const float4* gB = (const float4*)&E[(size_t)(colBase + lr) * DV] + lq4;

    float4 pa[4], pb[4];
#pragma unroll
    for (int q = 0; q < 4; q++) { pa[q] = __ldg(gA + q); pb[q] = __ldg(gB + q); }

#pragma unroll 1
    for (int chunk = 0; chunk < 8; chunk++) {
        int buf = chunk & 1;
        // convert + store current chunk (16 halves = 2 uint4 per matrix)
        {
            uint4 ua, ub;
            ua.x = h2u(__floats2half2_rn(pa[0].x, pa[0].y));
            ua.y = h2u(__floats2half2_rn(pa[0].z, pa[0].w));
            ua.z = h2u(__floats2half2_rn(pa[1].x, pa[1].y));
            ua.w = h2u(__floats2half2_rn(pa[1].z, pa[1].w));
            *(uint4*)&As[buf][lr * SL2 + (tid & 1) * 16] = ua;
            ua.x = h2u(__floats2half2_rn(pa[2].x, pa[2].y));
            ua.y = h2u(__floats2half2_rn(pa[2].z, pa[2].w));
            ua.z = h2u(__floats2half2_rn(pa[3].x, pa[3].y));
            ua.w = h2u(__floats2half2_rn(pa[3].z, pa[3].w));
            *(uint4*)&As[buf][lr * SL2 + (tid & 1) * 16 + 8] = ua;
            ub.x = h2u(__floats2half2_rn(pb[0].x, pb[0].y));
            ub.y = h2u(__floats2half2_rn(pb[0].z, pb[0].w));
            ub.z = h2u(__floats2half2_rn(pb[1].x, pb[1].y));
            ub.w = h2u(__floats2half2_rn(pb[1].z, pb[1].w));
            *(uint4*)&Bs[buf][lr * SL2 + (tid & 1) * 16] = ub;
            ub.x = h2u(__floats2half2_rn(pb[2].x, pb[2].y));
            ub.y = h2u(__floats2half2_rn(pb[2].z, pb[2].w));
            ub.z = h2u(__floats2half2_rn(pb[3].x, pb[3].y));
            ub.w = h2u(__floats2half2_rn(pb[3].z, pb[3].w));
            *(uint4*)&Bs[buf][lr * SL2 + (tid & 1) * 16 + 8] = ub;
        }
        __syncthreads();

        // prefetch next chunk
        if (chunk < 7) {
            int koff = (chunk + 1) * 8;   // float4 units
#pragma unroll
            for (int q = 0; q < 4; q++) {
                pa[q] = __ldg(gA + koff + q);
                pb[q] = __ldg(gB + koff + q);
            }
        }

        // compute: 2 k16-steps on buf
        const unsigned short* Ah = As[buf];
        const unsigned short* Bh = Bs[buf];
#pragma unroll
        for (int ks = 0; ks < 2; ks++) {
            int kk = ks * 16;
            uint32_t aF[2][4];
#pragma unroll
            for (int mt = 0; mt < 2; mt++) {
                int m = warpM * 32 + mt * 16;
                aF[mt][0] = *(const uint32_t*)&Ah[(m + fr) * SL2 + kk + 2 * fc];
                aF[mt][1] = *(const uint32_t*)&Ah[(m + fr + 8) * SL2 + kk + 2 * fc];
                aF[mt][2] = *(const uint32_t*)&Ah[(m + fr) * SL2 + kk + 2 * fc + 8];
                aF[mt][3] = *(const uint32_t*)&Ah[(m + fr + 8) * SL2 + kk + 2 * fc + 8];
            }
#pragma unroll
            for (int nt = 0; nt < 8; nt++) {
                int n = warpN * 64 + nt * 8 + fr;
                uint32_t b0 = *(const uint32_t*)&Bh[n * SL2 + kk + 2 * fc];
                uint32_t b1 = *(const uint32_t*)&Bh[n * SL2 + kk + 2 * fc + 8];
#pragma unroll
                for (int mt = 0; mt < 2; mt++)
                    mma_f16(acc[mt][nt], aF[mt][0], aF[mt][1], aF[mt][2], aF[mt][3], b0, b1);
            }
        }
        __syncthreads();
    }

    // ---- direct write: packed 16-bit keys (covers diag tile fully) ----
    int c2 = (lane & 3) * 2;
#pragma unroll
    for (int mt = 0; mt < 2; mt++) {
        int row = rowBase + warpM * 32 + mt * 16 + fr;
        int br0 = __ldg(&bid[row]);
        int br1 = __ldg(&bid[row + 8]);
#pragma unroll
        for (int nt = 0; nt < 8; nt++) {
            int col = colBase + warpN * 64 + nt * 8 + c2;
            int bc0 = __ldg(&bid[col]);
            int bc1 = __ldg(&bid[col + 1]);
            unsigned p00 = pack_p(acc[mt][nt][0], bc0 == br0);
            unsigned p01 = pack_p(acc[mt][nt][1], bc1 == br0);
            unsigned p10 = pack_p(acc[mt][nt][2], bc0 == br1);
            unsigned p11 = pack_p(acc[mt][nt][3], bc1 == br1);
            *(uint32_t*)&g_p16[(size_t)row * NV + col] = p00 | (p01 << 16);
            *(uint32_t*)&g_p16[(size_t)(row + 8) * NV + col] = p10 | (p11 << 16);
        }
    }

    // ---- mirror write (bx > by): stage packed keys (flag/value symmetric) ----
    if (bx > by) {
        unsigned short* smT = smh;
#pragma unroll 1
        for (int half = 0; half < 2; half++) {
            __syncthreads();
            if (warpN == half) {
#pragma unroll
                for (int mt = 0; mt < 2; mt++) {
                    int row = rowBase + warpM * 32 + mt * 16 + fr;
                    int br0 = __ldg(&bid[row]);
                    int br1 = __ldg(&bid[row + 8]);
                    int lrr = warpM * 32 + mt * 16 + fr;
#pragma unroll
                    for (int nt = 0; nt < 8; nt++) {
                        int col = colBase + half * 64 + nt * 8 + c2;
                        int bc0 = __ldg(&bid[col]);
                        int bc1 = __ldg(&bid[col + 1]);
                        int lc = nt * 8 + c2;
                        smT[lc * STS2 + lrr]           = (unsigned short)pack_p(acc[mt][nt][0], bc0 == br0);
                        smT[(lc + 1) * STS2 + lrr]     = (unsigned short)pack_p(acc[mt][nt][1], bc1 == br0);
                        smT[lc * STS2 + lrr + 8]       = (unsigned short)pack_p(acc[mt][nt][2], bc0 == br1);
                        smT[(lc + 1) * STS2 + lrr + 8] = (unsigned short)pack_p(acc[mt][nt][3], bc1 == br1);
                    }
                }
            }
            __syncthreads();
#pragma unroll
            for (int ii = 0; ii < 4; ii++) {
                int it = tid + ii * 256;
                int c = it >> 4;
                int g = it & 15;
                int j = colBase + half * 64 + c;
                uint4 v = *(uint4*)&smT[c * STS2 + g * 8];
                *(uint4*)&g_p16[(size_t)j * NV + rowBase + g * 8] = v;
            }
        }
    }
}

// ============================================================================
// Phase 2: coarse tournament top-k on packed 16-bit keys (unchanged)
// ============================================================================
__device__ __forceinline__ unsigned f2ord(float f) {
    unsigned b = __float_as_uint(f);
    return (b & 0x80000000u) ? ~b : (b | 0x80000000u);
}

__global__ void __launch_bounds__(256) topk_kernel() {
    int i = blockIdx.x;
    int tid = threadIdx.x;
    int lane = tid & 31;
    int wid = tid >> 5;

    __shared__ unsigned short sp[NV];
    __shared__ unsigned cm0[64], cm1[64];
    __shared__ int chosen[NC];

    const uint4* row = (const uint4*)&g_p16[(size_t)i * NV];
    for (int t = tid; t < NV / 8; t += 256) ((uint4*)sp)[t] = __ldg(&row[t]);
    __syncthreads();

#pragma unroll
    for (int cc = 0; cc < 8; cc++) {
        int c = wid * 8 + cc;
        int j1 = c * 64 + lane;
        int j2 = j1 + 32;
        unsigned k1 = ((unsigned)sp[j1] << 13) | (unsigned)(NV - j1);
        unsigned k2 = ((unsigned)sp[j2] << 13) | (unsigned)(NV - j2);
        unsigned m0 = __reduce_max_sync(0xffffffffu, k1 > k2 ? k1 : k2);
        unsigned x1 = k1 ^ FB, x2 = k2 ^ FB;
        unsigned m1 = __reduce_max_sync(0xffffffffu, x1 > x2 ? x1 : x2);
        if (lane == 0) { cm0[c] = m0; cm1[c] = m1; }
    }
    __syncthreads();

    if (wid == 0) {
#pragma unroll 1
        for (int phase = 0; phase < 2; phase++) {
            unsigned* cm = phase ? cm1 : cm0;
            unsigned xm = phase ? FB : 0u;
            int cnt  = phase ? NE : NI;
            int base = phase ? NI : 0;
#pragma unroll 1
            for (int t = 0; t < cnt; t++) {
                unsigned a = cm[lane];
                unsigned b = cm[lane + 32];
                unsigned m = __reduce_max_sync(0xffffffffu, a > b ? a : b);
                int j = NV - (int)(m & 0x1FFFu);
                int c = j >> 6;
                if (lane == 0) {
                    chosen[base + t] = j;
                    sp[j] = 0x8000;
                }
                __syncwarp();
                int j1 = c * 64 + lane;
                int j2 = j1 + 32;
                unsigned k1 = (((unsigned)sp[j1] << 13) | (unsigned)(NV - j1)) ^ xm;
                unsigned k2 = (((unsigned)sp[j2] << 13) | (unsigned)(NV - j2)) ^ xm;
                unsigned rm = __reduce_max_sync(0xffffffffu, k1 > k2 ? k1 : k2);
                if (lane == 0) cm[c] = rm;
                __syncwarp();
            }
        }
    }
    __syncthreads();

    if (tid < NC) g_cand[i * NC + tid] = chosen[tid];
}

// ============================================================================
// Phase 3: EXACT rescore (k-ascending sequential fmaf == reference chain).
// ============================================================================
__global__ void __launch_bounds__(256) rescore_kernel(const float* __restrict__ E) {
    int tid = threadIdx.x;
    int grp = tid >> 6;
    int sub = tid & 63;
    int row = blockIdx.x * 4 + grp;

    __shared__ float4 EiS[4][64];
    __shared__ int    candS[4][NC];
    __shared__ ull    keyS[4][NC];
    __shared__ int    knnS[4][NSEL];

    EiS[grp][sub] = __ldg((const float4*)&E[(size_t)row * DV] + sub);
    if (sub < NC) candS[grp][sub] = g_cand[row * NC + sub];
    __syncthreads();

    if (sub < NC) {
        int j = candS[grp][sub];
        const float4* Ej4 = (const float4*)&E[(size_t)j * DV];
        const float* Ei = (const float*)&EiS[grp][0];
        float acc = 0.0f;
#pragma unroll 4
        for (int k4 = 0; k4 < 64; k4++) {
            float4 b = __ldg(&Ej4[k4]);
            acc = fmaf(Ei[k4 * 4 + 0], b.x, acc);
            acc = fmaf(Ei[k4 * 4 + 1], b.y, acc);
            acc = fmaf(Ei[k4 * 4 + 2], b.z, acc);
            acc = fmaf(Ei[k4 * 4 + 3], b.w, acc);
        }
        keyS[grp][sub] = ((ull)f2ord(acc) << 13) | (unsigned)(NV - j);
    }
    __syncthreads();

    if (sub < NC) {
        int lo = (sub < NI) ? 0 : NI;
        int hi = (sub < NI) ? NI : NC;
        ull mykey = keyS[grp][sub];
        int r = 0;
        for (int u = lo; u < hi; u++)
            if (keyS[grp][u] > mykey) r++;
        int j = candS[grp][sub];
        if (sub < NI) {
            if (r >= 1 && r <= TK) knnS[grp][r - 1] = j;
        } else {
            if (r < TKI) knnS[grp][TK + r] = j;
        }
    }
    __syncthreads();

    if (sub < NSEL) g_knn[row * NSEL + sub] = knnS[grp][sub];

    unsigned b0 = 0, b1 = 0;
    int w0 = sub * 2;
#pragma unroll
    for (int t = 0; t < NSEL; t++) {
        int j = knnS[grp][t];
        int wi = j >> 5;
        unsigned bit = 1u << (j & 31);
        if (wi == w0) b0 |= bit;
        if (wi == w0 + 1) b1 |= bit;
    }
    g_bits[row * NW + w0] = b0;
    g_bits[row * NW + w0 + 1] = b1;
}

// ============================================================================
// Phase 4: mutual check -> scatter locality + all_close
// ============================================================================
__global__ void __launch_bounds__(256) finalize_kernel(
    const float* __restrict__ adj, const int* __restrict__ cl,
    float* __restrict__ out) {
    int id = blockIdx.x * blockDim.x + threadIdx.x;
    if (id >= NV * NSEL) return;
    int i = id / NSEL;
    int j = g_knn[id];

    bool mut = (j != i) && ((g_bits[j * NW + (i >> 5)] >> (i & 31)) & 1u);
    if (mut) out[(size_t)i * NV + j] = adj[(size_t)i * NV + j];

    bool ac = mut;
    if (!ac) {
        ac = true;
#pragma unroll
        for (int m = 0; m < MLAB; m++)
            if (cl[m * NV + i] != cl[m * NV + j]) ac = false;
    }
    out[(size_t)NV * NV + id] = ac ? 1.0f : 0.0f;
}

// ============================================================================
extern "C" void kernel_launch(void* const* d_in, const int* in_sizes, int n_in,
                              void* d_out, int out_size) {
    const float* adj = (const float*)d_in[0];
    const float* E   = (const float*)d_in[1];
    const int*   bid = (const int*)d_in[2];
    const int*   cl  = (const int*)d_in[3];
    float* out = (float*)d_out;

    cudaFuncSetAttribute(gemm_f16_kernel, cudaFuncAttributeMaxDynamicSharedMemorySize,
                         GSMEM_BYTES);

    cudaMemsetAsync(out, 0, (size_t)NV * NV * sizeof(float));
    dim3 grid(NV / 128, NV / 128);
    gemm_f16_kernel<<<grid, 256, GSMEM_BYTES>>>(E, bid);
    topk_kernel<<<NV, 256>>>();
    rescore_kernel<<<NV / 4, 256>>>(E);
    finalize_kernel<<<(NV * NSEL + 255) / 256, 256>>>(adj, cl, out);
}

// round 13
// speedup vs baseline: 1.7104x; 1.0180x over previous
#include <cuda_runtime.h>
#include <cuda_fp16.h>
#include <cstdint>
#include <math_constants.h>

#define NV   4096
#define DV   256
#define TK   20
#define TKI  10
#define NSEL 30
#define MLAB 5
#define NW   (NV/32)
#define NI   26
#define NE   14
#define NC   (NI + NE)
#define FB   (1u << 28)

typedef unsigned long long ull;

// -------- scratch (static device globals; no allocation) --------
__device__ unsigned short g_p16[(size_t)NV * NV];  // 32 MB packed coarse keys
__device__ int      g_cand[NV * NC];
__device__ int      g_knn[NV * NSEL];
__device__ unsigned g_bits[NV * NW];

// ============================================================================
// Phase 1: coarse sim via fp16 mma.sync m16n8k16 + ldmatrix fragment loads,
// double-buffered with ONE sync per chunk. Epilogue packs 16-bit keys.
// ============================================================================
#define SL2 40                          // slab row stride in halves
#define SLABH (128 * SL2)
#define GSMEM_BYTES (4 * SLABH * 2)     // A[2], B[2] fp16 = 40960 B
#define STS2 136                        // ushort mirror staging stride

__device__ __forceinline__ uint32_t h2u(__half2 h) { return *(uint32_t*)&h; }

__device__ __forceinline__ void mma_f16(float d[4], uint32_t a0, uint32_t a1,
                                        uint32_t a2, uint32_t a3,
                                        uint32_t b0, uint32_t b1) {
    asm volatile(
        "mma.sync.aligned.m16n8k16.row.col.f32.f16.f16.f32 "
        "{%0,%1,%2,%3}, {%4,%5,%6,%7}, {%8,%9}, {%0,%1,%2,%3};"
        : "+f"(d[0]), "+f"(d[1]), "+f"(d[2]), "+f"(d[3])
        : "r"(a0), "r"(a1), "r"(a2), "r"(a3), "r"(b0), "r"(b1));
}

__device__ __forceinline__ void ldsm_x4(uint32_t& r0, uint32_t& r1, uint32_t& r2,
                                        uint32_t& r3, uint32_t addr) {
    asm volatile("ldmatrix.sync.aligned.m8n8.x4.shared.b16 {%0,%1,%2,%3}, [%4];"
                 : "=r"(r0), "=r"(r1), "=r"(r2), "=r"(r3) : "r"(addr));
}

__device__ __forceinline__ unsigned pack_p(float v, bool same) {
    unsigned u = __half_as_ushort(__float2half_rn(v));
    unsigned o = (u & 0x8000u) ? ((~u) & 0xFFFFu) : (u | 0x8000u);
    return (same ? 0x8000u : 0u) | (o >> 1);
}

__global__ void __launch_bounds__(256, 2) gemm_f16_kernel(const float* __restrict__ E,
                                                          const int* __restrict__ bid) {
    int bx = blockIdx.x;
    int by = blockIdx.y;
    if (bx < by) return;

    extern __shared__ __align__(16) unsigned short smh[];
    unsigned short* As[2] = {smh, smh + SLABH};
    unsigned short* Bs[2] = {smh + 2 * SLABH, smh + 3 * SLABH};

    int tid = threadIdx.x;
    int lane = tid & 31;
    int wid = tid >> 5;
    int warpM = wid & 3;
    int warpN = wid >> 2;

    int rowBase = by * 128;
    int colBase = bx * 128;

    float acc[2][8][4];
#pragma unroll
    for (int mt = 0; mt < 2; mt++)
#pragma unroll
        for (int nt = 0; nt < 8; nt++)
#pragma unroll
            for (int g = 0; g < 4; g++) acc[mt][nt][g] = 0.0f;

    int fr = lane >> 2;

    // ldmatrix lane->address components
    int aRow = lane & 15;                         // A: row offset within 16
    int aColHalf = (lane >= 16) ? 8 : 0;          // A: k offset 0 or 8
    int bSeg = lane >> 3;                         // B: 0..3
    int bRow = (lane & 7) + ((bSeg >= 2) ? 8 : 0);
    int bColHalf = (bSeg & 1) ? 8 : 0;

    // loader: 2 threads per row, 16 floats each per 32-k chunk
    int lr = tid >> 1;
    int lq16 = (tid & 1) * 16;
    const float4* gA = (const float4*)&E[(size_t)(rowBase + lr) * DV] + (tid & 1) * 4;
    const float4* gB = (const float4*)&E[(size_t)(colBase + lr) * DV] + (tid & 1) * 4;

    float4 pa[4], pb[4];
#pragma unroll
    for (int q = 0; q < 4; q++) { pa[q] = __ldg(gA + q); pb[q] = __ldg(gB + q); }

    // store chunk 0 into buf 0
    {
        uint4 u;
        u.x = h2u(__floats2half2_rn(pa[0].x, pa[0].y));
        u.y = h2u(__floats2half2_rn(pa[0].z, pa[0].w));
        u.z = h2u(__floats2half2_rn(pa[1].x, pa[1].y));
        u.w = h2u(__floats2half2_rn(pa[1].z, pa[1].w));
        *(uint4*)&As[0][lr * SL2 + lq16] = u;
        u.x = h2u(__floats2half2_rn(pa[2].x, pa[2].y));
        u.y = h2u(__floats2half2_rn(pa[2].z, pa[2].w));
        u.z = h2u(__floats2half2_rn(pa[3].x, pa[3].y));
        u.w = h2u(__floats2half2_rn(pa[3].z, pa[3].w));
        *(uint4*)&As[0][lr * SL2 + lq16 + 8] = u;
        u.x = h2u(__floats2half2_rn(pb[0].x, pb[0].y));
        u.y = h2u(__floats2half2_rn(pb[0].z, pb[0].w));
        u.z = h2u(__floats2half2_rn(pb[1].x, pb[1].y));
        u.w = h2u(__floats2half2_rn(pb[1].z, pb[1].w));
        *(uint4*)&Bs[0][lr * SL2 + lq16] = u;
        u.x = h2u(__floats2half2_rn(pb[2].x, pb[2].y));
        u.y = h2u(__floats2half2_rn(pb[2].z, pb[2].w));
        u.z = h2u(__floats2half2_rn(pb[3].x, pb[3].y));
        u.w = h2u(__floats2half2_rn(pb[3].z, pb[3].w));
        *(uint4*)&Bs[0][lr * SL2 + lq16 + 8] = u;
    }
    __syncthreads();

#pragma unroll 1
    for (int chunk = 0; chunk < 8; chunk++) {
        int buf = chunk & 1;
        // prefetch next chunk into registers
        if (chunk < 7) {
            int koff = (chunk + 1) * 8;
#pragma unroll
            for (int q = 0; q < 4; q++) {
                pa[q] = __ldg(gA + koff + q);
                pb[q] = __ldg(gB + koff + q);
            }
        }

        // compute on buf (ldmatrix fragment loads)
        const unsigned short* Ah = As[buf];
        const unsigned short* Bh = Bs[buf];
        uint32_t aBase = (uint32_t)__cvta_generic_to_shared(Ah);
        uint32_t bBase = (uint32_t)__cvta_generic_to_shared(Bh);
#pragma unroll
        for (int ks = 0; ks < 2; ks++) {
            int kk = ks * 16;
            uint32_t aF[2][4];
#pragma unroll
            for (int mt = 0; mt < 2; mt++) {
                int m = warpM * 32 + mt * 16;
                uint32_t addr = aBase + (uint32_t)(((m + aRow) * SL2 + kk + aColHalf) * 2);
                ldsm_x4(aF[mt][0], aF[mt][1], aF[mt][2], aF[mt][3], addr);
            }
#pragma unroll
            for (int p = 0; p < 4; p++) {
                int n0 = warpN * 64 + p * 16;
                uint32_t addr = bBase + (uint32_t)(((n0 + bRow) * SL2 + kk + bColHalf) * 2);
                uint32_t b0, b1, b2, b3;
                ldsm_x4(b0, b1, b2, b3, addr);
#pragma unroll
                for (int mt = 0; mt < 2; mt++) {
                    mma_f16(acc[mt][p * 2],     aF[mt][0], aF[mt][1], aF[mt][2], aF[mt][3], b0, b1);
                    mma_f16(acc[mt][p * 2 + 1], aF[mt][0], aF[mt][1], aF[mt][2], aF[mt][3], b2, b3);
                }
            }
        }

        // store next chunk into other buffer, single sync
        if (chunk < 7) {
            int nb = buf ^ 1;
            uint4 u;
            u.x = h2u(__floats2half2_rn(pa[0].x, pa[0].y));
            u.y = h2u(__floats2half2_rn(pa[0].z, pa[0].w));
            u.z = h2u(__floats2half2_rn(pa[1].x, pa[1].y));
            u.w = h2u(__floats2half2_rn(pa[1].z, pa[1].w));
            *(uint4*)&As[nb][lr * SL2 + lq16] = u;
            u.x = h2u(__floats2half2_rn(pa[2].x, pa[2].y));
            u.y = h2u(__floats2half2_rn(pa[2].z, pa[2].w));
            u.z = h2u(__floats2half2_rn(pa[3].x, pa[3].y));
            u.w = h2u(__floats2half2_rn(pa[3].z, pa[3].w));
            *(uint4*)&As[nb][lr * SL2 + lq16 + 8] = u;
            u.x = h2u(__floats2half2_rn(pb[0].x, pb[0].y));
            u.y = h2u(__floats2half2_rn(pb[0].z, pb[0].w));
            u.z = h2u(__floats2half2_rn(pb[1].x, pb[1].y));
            u.w = h2u(__floats2half2_rn(pb[1].z, pb[1].w));
            *(uint4*)&Bs[nb][lr * SL2 + lq16] = u;
            u.x = h2u(__floats2half2_rn(pb[2].x, pb[2].y));
            u.y = h2u(__floats2half2_rn(pb[2].z, pb[2].w));
            u.z = h2u(__floats2half2_rn(pb[3].x, pb[3].y));
            u.w = h2u(__floats2half2_rn(pb[3].z, pb[3].w));
            *(uint4*)&Bs[nb][lr * SL2 + lq16 + 8] = u;
            __syncthreads();
        }
    }

    // ---- direct write: packed 16-bit keys (covers diag tile fully) ----
    int c2 = (lane & 3) * 2;
#pragma unroll
    for (int mt = 0; mt < 2; mt++) {
        int row = rowBase + warpM * 32 + mt * 16 + fr;
        int br0 = __ldg(&bid[row]);
        int br1 = __ldg(&bid[row + 8]);
#pragma unroll
        for (int nt = 0; nt < 8; nt++) {
            int col = colBase + warpN * 64 + nt * 8 + c2;
            int bc0 = __ldg(&bid[col]);
            int bc1 = __ldg(&bid[col + 1]);
            unsigned p00 = pack_p(acc[mt][nt][0], bc0 == br0);
            unsigned p01 = pack_p(acc[mt][nt][1], bc1 == br0);
            unsigned p10 = pack_p(acc[mt][nt][2], bc0 == br1);
            unsigned p11 = pack_p(acc[mt][nt][3], bc1 == br1);
            *(uint32_t*)&g_p16[(size_t)row * NV + col] = p00 | (p01 << 16);
            *(uint32_t*)&g_p16[(size_t)(row + 8) * NV + col] = p10 | (p11 << 16);
        }
    }

    // ---- mirror write (bx > by): stage packed keys (flag/value symmetric) ----
    if (bx > by) {
        unsigned short* smT = smh;
#pragma unroll 1
        for (int half = 0; half < 2; half++) {
            __syncthreads();
            if (warpN == half) {
#pragma unroll
                for (int mt = 0; mt < 2; mt++) {
                    int row = rowBase + warpM * 32 + mt * 16 + fr;
                    int br0 = __ldg(&bid[row]);
                    int br1 = __ldg(&bid[row + 8]);
                    int lrr = warpM * 32 + mt * 16 + fr;
#pragma unroll
                    for (int nt = 0; nt < 8; nt++) {
                        int col = colBase + half * 64 + nt * 8 + c2;
                        int bc0 = __ldg(&bid[col]);
                        int bc1 = __ldg(&bid[col + 1]);
                        int lc = nt * 8 + c2;
                        smT[lc * STS2 + lrr]           = (unsigned short)pack_p(acc[mt][nt][0], bc0 == br0);
                        smT[(lc + 1) * STS2 + lrr]     = (unsigned short)pack_p(acc[mt][nt][1], bc1 == br0);
                        smT[lc * STS2 + lrr + 8]       = (unsigned short)pack_p(acc[mt][nt][2], bc0 == br1);
                        smT[(lc + 1) * STS2 + lrr + 8] = (unsigned short)pack_p(acc[mt][nt][3], bc1 == br1);
                    }
                }
            }
            __syncthreads();
#pragma unroll
            for (int ii = 0; ii < 4; ii++) {
                int it = tid + ii * 256;
                int c = it >> 4;
                int g = it & 15;
                int j = colBase + half * 64 + c;
                uint4 v = *(uint4*)&smT[c * STS2 + g * 8];
                *(uint4*)&g_p16[(size_t)j * NV + rowBase + g * 8] = v;
            }
        }
    }
}

// ============================================================================
// Phase 2: coarse tournament top-k on packed 16-bit keys (unchanged)
// ============================================================================
__device__ __forceinline__ unsigned f2ord(float f) {
    unsigned b = __float_as_uint(f);
    return (b & 0x80000000u) ? ~b : (b | 0x80000000u);
}

__global__ void __launch_bounds__(256) topk_kernel() {
    int i = blockIdx.x;
    int tid = threadIdx.x;
    int lane = tid & 31;
    int wid = tid >> 5;

    __shared__ unsigned short sp[NV];
    __shared__ unsigned cm0[64], cm1[64];
    __shared__ int chosen[NC];

    const uint4* row = (const uint4*)&g_p16[(size_t)i * NV];
    for (int t = tid; t < NV / 8; t += 256) ((uint4*)sp)[t] = __ldg(&row[t]);
    __syncthreads();

#pragma unroll
    for (int cc = 0; cc < 8; cc++) {
        int c = wid * 8 + cc;
        int j1 = c * 64 + lane;
        int j2 = j1 + 32;
        unsigned k1 = ((unsigned)sp[j1] << 13) | (unsigned)(NV - j1);
        unsigned k2 = ((unsigned)sp[j2] << 13) | (unsigned)(NV - j2);
        unsigned m0 = __reduce_max_sync(0xffffffffu, k1 > k2 ? k1 : k2);
        unsigned x1 = k1 ^ FB, x2 = k2 ^ FB;
        unsigned m1 = __reduce_max_sync(0xffffffffu, x1 > x2 ? x1 : x2);
        if (lane == 0) { cm0[c] = m0; cm1[c] = m1; }
    }
    __syncthreads();

    if (wid == 0) {
#pragma unroll 1
        for (int phase = 0; phase < 2; phase++) {
            unsigned* cm = phase ? cm1 : cm0;
            unsigned xm = phase ? FB : 0u;
            int cnt  = phase ? NE : NI;
            int base = phase ? NI : 0;
#pragma unroll 1
            for (int t = 0; t < cnt; t++) {
                unsigned a = cm[lane];
                unsigned b = cm[lane + 32];
                unsigned m = __reduce_max_sync(0xffffffffu, a > b ? a : b);
                int j = NV - (int)(m & 0x1FFFu);
                int c = j >> 6;
                if (lane == 0) {
                    chosen[base + t] = j;
                    sp[j] = 0x8000;
                }
                __syncwarp();
                int j1 = c * 64 + lane;
                int j2 = j1 + 32;
                unsigned k1 = (((unsigned)sp[j1] << 13) | (unsigned)(NV - j1)) ^ xm;
                unsigned k2 = (((unsigned)sp[j2] << 13) | (unsigned)(NV - j2)) ^ xm;
                unsigned rm = __reduce_max_sync(0xffffffffu, k1 > k2 ? k1 : k2);
                if (lane == 0) cm[c] = rm;
                __syncwarp();
            }
        }
    }
    __syncthreads();

    if (tid < NC) g_cand[i * NC + tid] = chosen[tid];
}

// ============================================================================
// Phase 3: EXACT rescore (k-ascending sequential fmaf == reference chain).
// ============================================================================
__global__ void __launch_bounds__(256) rescore_kernel(const float* __restrict__ E) {
    int tid = threadIdx.x;
    int grp = tid >> 6;
    int sub = tid & 63;
    int row = blockIdx.x * 4 + grp;

    __shared__ float4 EiS[4][64];
    __shared__ int    candS[4][NC];
    __shared__ ull    keyS[4][NC];
    __shared__ int    knnS[4][NSEL];

    EiS[grp][sub] = __ldg((const float4*)&E[(size_t)row * DV] + sub);
    if (sub < NC) candS[grp][sub] = g_cand[row * NC + sub];
    __syncthreads();

    if (sub < NC) {
        int j = candS[grp][sub];
        const float4* Ej4 = (const float4*)&E[(size_t)j * DV];
        const float* Ei = (const float*)&EiS[grp][0];
        float acc = 0.0f;
#pragma unroll 4
        for (int k4 = 0; k4 < 64; k4++) {
            float4 b = __ldg(&Ej4[k4]);
            acc = fmaf(Ei[k4 * 4 + 0], b.x, acc);
            acc = fmaf(Ei[k4 * 4 + 1], b.y, acc);
            acc = fmaf(Ei[k4 * 4 + 2], b.z, acc);
            acc = fmaf(Ei[k4 * 4 + 3], b.w, acc);
        }
        keyS[grp][sub] = ((ull)f2ord(acc) << 13) | (unsigned)(NV - j);
    }
    __syncthreads();

    if (sub < NC) {
        int lo = (sub < NI) ? 0 : NI;
        int hi = (sub < NI) ? NI : NC;
        ull mykey = keyS[grp][sub];
        int r = 0;
        for (int u = lo; u < hi; u++)
            if (keyS[grp][u] > mykey) r++;
        int j = candS[grp][sub];
        if (sub < NI) {
            if (r >= 1 && r <= TK) knnS[grp][r - 1] = j;
        } else {
            if (r < TKI) knnS[grp][TK + r] = j;
        }
    }
    __syncthreads();

    if (sub < NSEL) g_knn[row * NSEL + sub] = knnS[grp][sub];

    unsigned b0 = 0, b1 = 0;
    int w0 = sub * 2;
#pragma unroll
    for (int t = 0; t < NSEL; t++) {
        int j = knnS[grp][t];
        int wi = j >> 5;
        unsigned bit = 1u << (j & 31);
        if (wi == w0) b0 |= bit;
        if (wi == w0 + 1) b1 |= bit;
    }
    g_bits[row * NW + w0] = b0;
    g_bits[row * NW + w0 + 1] = b1;
}

// ============================================================================
// Phase 4: mutual check -> scatter locality + all_close
// ============================================================================
__global__ void __launch_bounds__(256) finalize_kernel(
    const float* __restrict__ adj, const int* __restrict__ cl,
    float* __restrict__ out) {
    int id = blockIdx.x * blockDim.x + threadIdx.x;
    if (id >= NV * NSEL) return;
    int i = id / NSEL;
    int j = g_knn[id];

    bool mut = (j != i) && ((g_bits[j * NW + (i >> 5)] >> (i & 31)) & 1u);
    if (mut) out[(size_t)i * NV + j] = adj[(size_t)i * NV + j];

    bool ac = mut;
    if (!ac) {
        ac = true;
#pragma unroll
        for (int m = 0; m < MLAB; m++)
            if (cl[m * NV + i] != cl[m * NV + j]) ac = false;
    }
    out[(size_t)NV * NV + id] = ac ? 1.0f : 0.0f;
}

// ============================================================================
extern "C" void kernel_launch(void* const* d_in, const int* in_sizes, int n_in,
                              void* d_out, int out_size) {
    const float* adj = (const float*)d_in[0];
    const float* E   = (const float*)d_in[1];
    const int*   bid = (const int*)d_in[2];
    const int*   cl  = (const int*)d_in[3];
    float* out = (float*)d_out;

    cudaFuncSetAttribute(gemm_f16_kernel, cudaFuncAttributeMaxDynamicSharedMemorySize,
                         GSMEM_BYTES);

    cudaMemsetAsync(out, 0, (size_t)NV * NV * sizeof(float));
    dim3 grid(NV / 128, NV / 128);
    gemm_f16_kernel<<<grid, 256, GSMEM_BYTES>>>(E, bid);
    topk_kernel<<<NV, 256>>>();
    rescore_kernel<<<NV / 4, 256>>>(E);
    finalize_kernel<<<(NV * NSEL + 255) / 256, 256>>>(adj, cl, out);
}